// round 5
// baseline (speedup 1.0000x reference)
#include <cuda_runtime.h>
#include <math.h>

// ---------------------------------------------------------------------------
// Problem constants
// ---------------------------------------------------------------------------
#define B_    16
#define T_    64
#define HW_   512
#define E_    256
#define E2_   512
#define V_    128
#define BT_   1024   // B*T
#define NBLK_ 3

typedef unsigned long long ull;

// ---------------------------------------------------------------------------
// Scratch (device globals: no allocation allowed)
// ---------------------------------------------------------------------------
__device__ __align__(16) float g_s   [BT_ * E_];       // embed(labels), fixed
__device__ __align__(16) float g_a   [BT_ * E_];       // running activation
__device__ __align__(16) float g_z   [BT_ * E_];       // GLU output
__device__ __align__(16) float g_res [B_ * HW_ * E_];  // enc + dec
__device__ __align__(16) float g_Wt  [E_ * E_];        // W_w transposed: Wt[i][o]
__device__ __align__(16) float g_Wop [E_ * V_];        // Wo interleaved e-pairs
__device__ __align__(16) float g_cw2 [3 * E_ * E2_];   // conv_w, GLU-interleaved cols
__device__ __align__(16) float g_cb2 [E2_];            // conv_b, interleaved
__device__ __align__(16) float g_decT[B_ * E_ * HW_];  // dec transposed [b][e][s]

// ---------------------------------------------------------------------------
// f32x2 packed math (sm_100+)
// ---------------------------------------------------------------------------
__device__ __forceinline__ ull pack2(float x, float y) {
    ull r; asm("mov.b64 %0, {%1,%2};" : "=l"(r) : "f"(x), "f"(y)); return r;
}
__device__ __forceinline__ void unpack2(ull v, float& x, float& y) {
    asm("mov.b64 {%0,%1}, %2;" : "=f"(x), "=f"(y) : "l"(v));
}
__device__ __forceinline__ ull ffma2(ull a, ull b, ull c) {
    ull d; asm("fma.rn.f32x2 %0, %1, %2, %3;" : "=l"(d) : "l"(a), "l"(b), "l"(c)); return d;
}

// ---------------------------------------------------------------------------
// K0: merged setup — embed | residual | weight-prep | dec transpose
// grid = 1024 + 2048 + 1153 + 2048 = 6273 blocks, 256 threads
// ---------------------------------------------------------------------------
#define NB_EMB  1024
#define NB_RES  2048
#define NB_PREP 1153
#define NB_TR   2048

__global__ __launch_bounds__(256) void k_setup(const int* __restrict__ labels,
                                               const float* __restrict__ emb,
                                               const float* __restrict__ enc,
                                               const float* __restrict__ dec,
                                               const float* __restrict__ Ww,
                                               const float* __restrict__ Wo,
                                               const float* __restrict__ cw,
                                               const float* __restrict__ cb) {
    int bid = blockIdx.x, tid = threadIdx.x;

    if (bid < NB_EMB) {
        // ---- embed: s = embed[labels]; a = s ----
        int row = bid, e = tid;
        int lbl = labels[row];
        float v = emb[lbl * E_ + e];
        g_s[row * E_ + e] = v;
        g_a[row * E_ + e] = v;
        return;
    }
    bid -= NB_EMB;

    if (bid < NB_RES) {
        // ---- residual = enc + dec ----
        int i = bid * 256 + tid;                     // float4 index
        float4 a = ((const float4*)enc)[i];
        float4 b = ((const float4*)dec)[i];
        float4 c;
        c.x = a.x + b.x; c.y = a.y + b.y; c.z = a.z + b.z; c.w = a.w + b.w;
        ((float4*)g_res)[i] = c;
        return;
    }
    bid -= NB_RES;

    if (bid < NB_PREP) {
        // ---- weight prep ----
        if (bid < E_) {
            g_Wt[tid * E_ + bid] = Ww[bid * E_ + tid];
        } else if (bid < E_ + V_) {
            int v = bid - E_;
            g_Wop[(tid >> 1) * (2 * V_) + 2 * v + (tid & 1)] = Wo[v * E_ + tid];
        } else if (bid < E_ + V_ + 3 * E_) {
            int kk = bid - (E_ + V_);
            #pragma unroll
            for (int h = 0; h < 2; ++h) {
                int c = tid + h * 256;
                int j = c >> 1, p = c & 1;
                g_cw2[kk * E2_ + c] = cw[kk * E2_ + p * E_ + j];
            }
        } else {
            #pragma unroll
            for (int h = 0; h < 2; ++h) {
                int c = tid + h * 256;
                int j = c >> 1, p = c & 1;
                g_cb2[c] = cb[p * E_ + j];
            }
        }
        return;
    }
    bid -= NB_PREP;

    // ---- transpose dec -> g_decT[b][e][s] ----
    {
        __shared__ float tile[32][33];
        int s0 = (bid & 15) << 5;
        int e0 = ((bid >> 4) & 7) << 5;
        int b  = bid >> 7;
        int tx = tid & 31, ty = tid >> 5;
        #pragma unroll
        for (int i = 0; i < 32; i += 8)
            tile[ty + i][tx] = dec[((b << 9) + s0 + ty + i) * E_ + e0 + tx];
        __syncthreads();
        #pragma unroll
        for (int i = 0; i < 32; i += 8)
            g_decT[((b << 8) + e0 + ty + i) * HW_ + s0 + tx] = tile[tx][ty + i];
    }
}

// ---------------------------------------------------------------------------
// K1: conv (K=3, pad 1) + bias + GLU   -> g_z
// GEMM: C[64m][64n] over kk=768; B pre-duplicated in smem for f32x2.
// grid 128 = 16 b * 8 n-tiles; 256 threads; thread tile 4m x 4n.
// ---------------------------------------------------------------------------
__global__ __launch_bounds__(256) void k_conv3() {
    __shared__ __align__(16) float As[2][16][68];    // [kc][m]
    __shared__ __align__(16) float Bs[2][16][136];   // [kc][dup'd cols], 64 cols x2

    int bb  = blockIdx.x >> 3;
    int n0  = (blockIdx.x & 7) << 6;
    int tid = threadIdx.x;
    int mA  = tid >> 2, qA  = tid & 3;   // A loader: row mA, ci group 4*qA
    int kB  = tid >> 5, nn2 = tid & 31;  // B loader: kc rows kB,kB+8; col-pair nn2
    int mi  = tid >> 4, ni  = tid & 15;  // compute mapping

    const float* abase = g_a + (bb << 6) * E_;

    // prologue: chunk 0 (k=0, ci0=0)
    {
        int ts = mA - 1;
        float4 v = make_float4(0.f, 0.f, 0.f, 0.f);
        if (ts >= 0) v = *(const float4*)&abase[ts * E_ + 4 * qA];
        As[0][4 * qA + 0][mA] = v.x;
        As[0][4 * qA + 1][mA] = v.y;
        As[0][4 * qA + 2][mA] = v.z;
        As[0][4 * qA + 3][mA] = v.w;
        #pragma unroll
        for (int it = 0; it < 2; ++it) {
            int kc = kB + it * 8;
            float2 w = *(const float2*)&g_cw2[kc * E2_ + n0 + 2 * nn2];
            *(float4*)&Bs[0][kc][4 * nn2] = make_float4(w.x, w.x, w.y, w.y);
        }
    }
    __syncthreads();

    ull acc[2][4];
    {
        float4 bj = *(const float4*)&g_cb2[n0 + ni * 4];
        acc[0][0] = acc[1][0] = pack2(bj.x, bj.x);
        acc[0][1] = acc[1][1] = pack2(bj.y, bj.y);
        acc[0][2] = acc[1][2] = pack2(bj.z, bj.z);
        acc[0][3] = acc[1][3] = pack2(bj.w, bj.w);
    }

    float4 aN; float2 bN0, bN1;
    for (int ch = 0; ch < 48; ++ch) {
        int cur = ch & 1;
        if (ch < 47) {
            int chn = ch + 1;
            int k   = chn >> 4;
            int ci0 = (chn & 15) << 4;
            int ts  = mA + k - 1;
            aN = make_float4(0.f, 0.f, 0.f, 0.f);
            if (ts >= 0 && ts < 64)
                aN = *(const float4*)&abase[ts * E_ + ci0 + 4 * qA];
            bN0 = *(const float2*)&g_cw2[((chn << 4) + kB    ) * E2_ + n0 + 2 * nn2];
            bN1 = *(const float2*)&g_cw2[((chn << 4) + kB + 8) * E2_ + n0 + 2 * nn2];
        }

        #pragma unroll
        for (int kc = 0; kc < 16; ++kc) {
            ulonglong2 av  = *(const ulonglong2*)&As[cur][kc][mi * 4];
            ulonglong2 b01 = *(const ulonglong2*)&Bs[cur][kc][8 * ni];
            ulonglong2 b23 = *(const ulonglong2*)&Bs[cur][kc][8 * ni + 4];
            acc[0][0] = ffma2(av.x, b01.x, acc[0][0]);
            acc[0][1] = ffma2(av.x, b01.y, acc[0][1]);
            acc[0][2] = ffma2(av.x, b23.x, acc[0][2]);
            acc[0][3] = ffma2(av.x, b23.y, acc[0][3]);
            acc[1][0] = ffma2(av.y, b01.x, acc[1][0]);
            acc[1][1] = ffma2(av.y, b01.y, acc[1][1]);
            acc[1][2] = ffma2(av.y, b23.x, acc[1][2]);
            acc[1][3] = ffma2(av.y, b23.y, acc[1][3]);
        }

        if (ch < 47) {
            int nxt = cur ^ 1;
            As[nxt][4 * qA + 0][mA] = aN.x;
            As[nxt][4 * qA + 1][mA] = aN.y;
            As[nxt][4 * qA + 2][mA] = aN.z;
            As[nxt][4 * qA + 3][mA] = aN.w;
            *(float4*)&Bs[nxt][kB    ][4 * nn2] = make_float4(bN0.x, bN0.x, bN0.y, bN0.y);
            *(float4*)&Bs[nxt][kB + 8][4 * nn2] = make_float4(bN1.x, bN1.x, bN1.y, bN1.y);
        }
        __syncthreads();
    }

    // epilogue: GLU pairs (col even = za, col odd = zb)
    int zj = (n0 >> 1) + (ni << 1);
    #pragma unroll
    for (int p = 0; p < 2; ++p) {
        float a0l, a0h, b0l, b0h, a1l, a1h, b1l, b1h;
        unpack2(acc[p][0], a0l, a0h);
        unpack2(acc[p][1], b0l, b0h);
        unpack2(acc[p][2], a1l, a1h);
        unpack2(acc[p][3], b1l, b1h);
        int m0 = mi * 4 + 2 * p;
        float* zr0 = g_z + ((bb << 6) + m0) * E_ + zj;
        float* zr1 = zr0 + E_;
        zr0[0] = a0l / (1.f + expf(-b0l));
        zr0[1] = a1l / (1.f + expf(-b1l));
        zr1[0] = a0h / (1.f + expf(-b0h));
        zr1[1] = a1h / (1.f + expf(-b1h));
    }
}

// ---------------------------------------------------------------------------
// K2: fused h-projection + attention.
//   phase 0: h = z @ W^T + Wb + s  (into smem qt)
//   phase 1: scores = h @ decT      phase 2: softmax
//   phase 3: a = softmax @ res + z  (z from smem)
// grid 128 = 16 b * 8 t-tiles; 256 threads
// ---------------------------------------------------------------------------
__global__ __launch_bounds__(256) void k_attn2(const float* __restrict__ Wb) {
    __shared__ __align__(16) float zt [E_][8];      // z transposed [i][t]
    __shared__ __align__(16) float qt [E_][8];      // h transposed [o][t]
    __shared__ __align__(16) float sst[HW_][8];     // scores [s][t]
    __shared__ float rsum[8];

    int b    = blockIdx.x >> 3;
    int t0   = (blockIdx.x & 7) << 3;
    int tid  = threadIdx.x;
    int lane = tid & 31;
    int wid  = tid >> 5;
    int row0 = (b << 6) + t0;

    // ---- phase 0a: z tile to smem ----
    #pragma unroll
    for (int r = 0; r < 8; ++r)
        zt[tid][r] = g_z[(row0 + r) * E_ + tid];
    __syncthreads();

    // ---- phase 0b: h = z @ W^T + Wb + s -> qt ----
    {
        ull hacc[4];
        #pragma unroll
        for (int p = 0; p < 4; ++p) hacc[p] = pack2(0.f, 0.f);

        #pragma unroll 8
        for (int i = 0; i < E_; ++i) {
            float wv = g_Wt[i * E_ + tid];
            ull wp = pack2(wv, wv);
            ulonglong2 z01 = *(const ulonglong2*)&zt[i][0];
            ulonglong2 z23 = *(const ulonglong2*)&zt[i][4];
            hacc[0] = ffma2(z01.x, wp, hacc[0]);
            hacc[1] = ffma2(z01.y, wp, hacc[1]);
            hacc[2] = ffma2(z23.x, wp, hacc[2]);
            hacc[3] = ffma2(z23.y, wp, hacc[3]);
        }
        float wb = Wb[tid];
        #pragma unroll
        for (int p = 0; p < 4; ++p) {
            float h0, h1; unpack2(hacc[p], h0, h1);
            int r = 2 * p;
            float q0 = h0 + wb + g_s[(row0 + r)     * E_ + tid];
            float q1 = h1 + wb + g_s[(row0 + r + 1) * E_ + tid];
            *(ull*)&qt[tid][r] = pack2(q0, q1);
        }
    }
    __syncthreads();

    // ---- phase 1: scores = h @ decT (thread owns s = tid, tid+256) ----
    {
        ull A0[4], A1[4];
        #pragma unroll
        for (int j = 0; j < 4; ++j) { A0[j] = pack2(0.f, 0.f); A1[j] = pack2(0.f, 0.f); }

        const float* kb = g_decT + ((size_t)b << 8) * HW_ + tid;
        #pragma unroll 4
        for (int e = 0; e < E_; ++e) {
            float k0 = kb[e * HW_];
            float k1 = kb[e * HW_ + 256];
            ull kp0 = pack2(k0, k0);
            ull kp1 = pack2(k1, k1);
            ulonglong2 q01 = *(const ulonglong2*)&qt[e][0];
            ulonglong2 q23 = *(const ulonglong2*)&qt[e][4];
            A0[0] = ffma2(q01.x, kp0, A0[0]);
            A0[1] = ffma2(q01.y, kp0, A0[1]);
            A0[2] = ffma2(q23.x, kp0, A0[2]);
            A0[3] = ffma2(q23.y, kp0, A0[3]);
            A1[0] = ffma2(q01.x, kp1, A1[0]);
            A1[1] = ffma2(q01.y, kp1, A1[1]);
            A1[2] = ffma2(q23.x, kp1, A1[2]);
            A1[3] = ffma2(q23.y, kp1, A1[3]);
        }
        ull* s0p = (ull*)&sst[tid][0];
        ull* s1p = (ull*)&sst[tid + 256][0];
        #pragma unroll
        for (int j = 0; j < 4; ++j) { s0p[j] = A0[j]; s1p[j] = A1[j]; }
    }
    __syncthreads();

    // ---- phase 2: softmax over s (warp wid handles t = wid) ----
    {
        int t = wid;
        float m = -1e30f;
        for (int s = lane; s < HW_; s += 32) m = fmaxf(m, sst[s][t]);
        #pragma unroll
        for (int off = 16; off; off >>= 1)
            m = fmaxf(m, __shfl_xor_sync(0xffffffffu, m, off));
        float sum = 0.f;
        for (int s = lane; s < HW_; s += 32) {
            float ev = expf(sst[s][t] - m);
            sst[s][t] = ev;
            sum += ev;
        }
        #pragma unroll
        for (int off = 16; off; off >>= 1)
            sum += __shfl_xor_sync(0xffffffffu, sum, off);
        if (lane == 0) rsum[t] = 1.f / sum;
    }
    __syncthreads();

    // ---- phase 3: c = (exp-scores @ res) * rsum; a = c + z ----
    {
        const float* resb = g_res + ((size_t)b * HW_) * E_;
        int e = tid;
        ull acc[4];
        #pragma unroll
        for (int p = 0; p < 4; ++p) acc[p] = pack2(0.f, 0.f);

        #pragma unroll 4
        for (int s = 0; s < HW_; ++s) {
            float rv = resb[s * E_ + e];
            ull rp = pack2(rv, rv);
            ulonglong2 a01 = *(const ulonglong2*)&sst[s][0];
            ulonglong2 a23 = *(const ulonglong2*)&sst[s][4];
            acc[0] = ffma2(a01.x, rp, acc[0]);
            acc[1] = ffma2(a01.y, rp, acc[1]);
            acc[2] = ffma2(a23.x, rp, acc[2]);
            acc[3] = ffma2(a23.y, rp, acc[3]);
        }

        #pragma unroll
        for (int p = 0; p < 4; ++p) {
            float c0, c1; unpack2(acc[p], c0, c1);
            int t = 2 * p;
            int idx = (row0 + t) * E_ + e;
            g_a[idx]      = c0 * rsum[t]     + zt[e][t];
            g_a[idx + E_] = c1 * rsum[t + 1] + zt[e][t + 1];
        }
    }
}

// ---------------------------------------------------------------------------
// K3: logits = a @ Wo^T + Wo_b; log_softmax over V  -> out
// ---------------------------------------------------------------------------
__global__ __launch_bounds__(128) void k_logits(const float* __restrict__ Wob,
                                                float* __restrict__ out) {
    __shared__ __align__(16) float av4[4][E_];
    __shared__ float redm[4][4], reds[4][4];

    int row0 = blockIdx.x * 4;
    int v    = threadIdx.x;
    int lane = v & 31;
    int wid  = v >> 5;

    #pragma unroll
    for (int r = 0; r < 4; ++r) {
        av4[r][v]       = g_a[(row0 + r) * E_ + v];
        av4[r][v + 128] = g_a[(row0 + r) * E_ + v + 128];
    }
    __syncthreads();

    ull acc[4];
    #pragma unroll
    for (int r = 0; r < 4; ++r) acc[r] = pack2(0.f, 0.f);

    const ull* wop = (const ull*)g_Wop;
    #pragma unroll 4
    for (int ep = 0; ep < E_ / 2; ++ep) {
        ull wp = wop[ep * V_ + v];
        #pragma unroll
        for (int r = 0; r < 4; ++r)
            acc[r] = ffma2(((const ull*)av4[r])[ep], wp, acc[r]);
    }

    float lg[4], wb = Wob[v];
    #pragma unroll
    for (int r = 0; r < 4; ++r) {
        float lo, hi; unpack2(acc[r], lo, hi);
        lg[r] = lo + hi + wb;
    }

    float wm[4];
    #pragma unroll
    for (int r = 0; r < 4; ++r) {
        wm[r] = lg[r];
        #pragma unroll
        for (int off = 16; off; off >>= 1)
            wm[r] = fmaxf(wm[r], __shfl_xor_sync(0xffffffffu, wm[r], off));
    }
    if (lane == 0) {
        #pragma unroll
        for (int r = 0; r < 4; ++r) redm[r][wid] = wm[r];
    }
    __syncthreads();
    float bm[4];
    #pragma unroll
    for (int r = 0; r < 4; ++r)
        bm[r] = fmaxf(fmaxf(redm[r][0], redm[r][1]), fmaxf(redm[r][2], redm[r][3]));

    float ws[4];
    #pragma unroll
    for (int r = 0; r < 4; ++r) {
        ws[r] = expf(lg[r] - bm[r]);
        #pragma unroll
        for (int off = 16; off; off >>= 1)
            ws[r] += __shfl_xor_sync(0xffffffffu, ws[r], off);
    }
    if (lane == 0) {
        #pragma unroll
        for (int r = 0; r < 4; ++r) reds[r][wid] = ws[r];
    }
    __syncthreads();

    #pragma unroll
    for (int r = 0; r < 4; ++r) {
        float bs = reds[r][0] + reds[r][1] + reds[r][2] + reds[r][3];
        out[(row0 + r) * V_ + v] = lg[r] - bm[r] - logf(bs);
    }
}

// ---------------------------------------------------------------------------
// kernel_launch
// ---------------------------------------------------------------------------
extern "C" void kernel_launch(void* const* d_in, const int* in_sizes, int n_in,
                              void* d_out, int out_size) {
    int li = 2;
    for (int i = 0; i < n_in; ++i)
        if (in_sizes[i] == 1024) { li = i; break; }

    const float *enc, *dec, *emb, *cw, *cb, *Ww, *Wb, *Wo, *Wob;
    const int* labels;
    if (li == 2) {
        enc = (const float*)d_in[0]; dec = (const float*)d_in[1];
        labels = (const int*)d_in[2];
        emb = (const float*)d_in[3]; cw  = (const float*)d_in[4];
        cb  = (const float*)d_in[5]; Ww  = (const float*)d_in[6];
        Wb  = (const float*)d_in[7]; Wo  = (const float*)d_in[8];
        Wob = (const float*)d_in[9];
    } else {
        enc = (const float*)d_in[0]; dec = (const float*)d_in[1];
        emb = (const float*)d_in[2]; cw  = (const float*)d_in[3];
        cb  = (const float*)d_in[4]; Ww  = (const float*)d_in[5];
        Wb  = (const float*)d_in[6]; Wo  = (const float*)d_in[7];
        Wob = (const float*)d_in[8];
        labels = (const int*)d_in[9];
    }
    float* out = (float*)d_out;

    k_setup<<<NB_EMB + NB_RES + NB_PREP + NB_TR, 256>>>(labels, emb, enc, dec,
                                                        Ww, Wo, cw, cb);

    for (int l = 0; l < NBLK_; ++l) {
        k_conv3<<<128, 256>>>();
        k_attn2<<<128, 256>>>(Wb);
    }

    k_logits<<<BT_ / 4, 128>>>(Wob, out);
}

// round 6
// speedup vs baseline: 1.4820x; 1.4820x over previous
#include <cuda_runtime.h>
#include <math.h>

// ---------------------------------------------------------------------------
// Problem constants
// ---------------------------------------------------------------------------
#define B_    16
#define T_    64
#define HW_   512
#define E_    256
#define E2_   512
#define V_    128
#define BT_   1024   // B*T
#define NBLK_ 3

typedef unsigned long long ull;

// ---------------------------------------------------------------------------
// Scratch (device globals: no allocation allowed)
// ---------------------------------------------------------------------------
__device__ __align__(16) float g_s   [BT_ * E_];       // embed(labels), fixed
__device__ __align__(16) float g_a   [BT_ * E_];       // running activation (row-major)
__device__ __align__(16) float g_aT  [B_ * E_ * T_];   // a transposed [b][e][t]
__device__ __align__(16) float g_z   [BT_ * E_];       // GLU output
__device__ __align__(16) float g_res [B_ * HW_ * E_];  // enc + dec
__device__ __align__(16) float g_Wt  [E_ * E_];        // W_w transposed: Wt[i][o]
__device__ __align__(16) float g_Wop [E_ * V_];        // Wo interleaved e-pairs
__device__ __align__(16) float g_cw2 [3 * E_ * E2_];   // conv_w, GLU-interleaved cols
__device__ __align__(16) float g_cb2 [E2_];            // conv_b, interleaved
__device__ __align__(16) float g_decT[B_ * E_ * HW_];  // dec transposed [b][e][s]
__device__ __align__(16) float g_part[3 * BT_ * E2_];  // conv split-k partials

// ---------------------------------------------------------------------------
// f32x2 packed math (sm_100+)
// ---------------------------------------------------------------------------
__device__ __forceinline__ ull pack2(float x, float y) {
    ull r; asm("mov.b64 %0, {%1,%2};" : "=l"(r) : "f"(x), "f"(y)); return r;
}
__device__ __forceinline__ void unpack2(ull v, float& x, float& y) {
    asm("mov.b64 {%0,%1}, %2;" : "=f"(x), "=f"(y) : "l"(v));
}
__device__ __forceinline__ ull ffma2(ull a, ull b, ull c) {
    ull d; asm("fma.rn.f32x2 %0, %1, %2, %3;" : "=l"(d) : "l"(a), "l"(b), "l"(c)); return d;
}

// ---------------------------------------------------------------------------
// K0: merged setup — embed | residual | weight-prep | dec transpose
// ---------------------------------------------------------------------------
#define NB_EMB  1024
#define NB_RES  2048
#define NB_PREP 1153
#define NB_TR   2048

__global__ __launch_bounds__(256) void k_setup(const int* __restrict__ labels,
                                               const float* __restrict__ emb,
                                               const float* __restrict__ enc,
                                               const float* __restrict__ dec,
                                               const float* __restrict__ Ww,
                                               const float* __restrict__ Wo,
                                               const float* __restrict__ cw,
                                               const float* __restrict__ cb) {
    int bid = blockIdx.x, tid = threadIdx.x;

    if (bid < NB_EMB) {
        // ---- embed: s = embed[labels]; a = s (both layouts) ----
        int row = bid, e = tid;
        int lbl = labels[row];
        float v = emb[lbl * E_ + e];
        g_s[row * E_ + e] = v;
        g_a[row * E_ + e] = v;
        g_aT[(row >> 6) * (E_ * T_) + e * T_ + (row & 63)] = v;
        return;
    }
    bid -= NB_EMB;

    if (bid < NB_RES) {
        int i = bid * 256 + tid;
        float4 a = ((const float4*)enc)[i];
        float4 b = ((const float4*)dec)[i];
        float4 c;
        c.x = a.x + b.x; c.y = a.y + b.y; c.z = a.z + b.z; c.w = a.w + b.w;
        ((float4*)g_res)[i] = c;
        return;
    }
    bid -= NB_RES;

    if (bid < NB_PREP) {
        if (bid < E_) {
            g_Wt[tid * E_ + bid] = Ww[bid * E_ + tid];
        } else if (bid < E_ + V_) {
            int v = bid - E_;
            g_Wop[(tid >> 1) * (2 * V_) + 2 * v + (tid & 1)] = Wo[v * E_ + tid];
        } else if (bid < E_ + V_ + 3 * E_) {
            int kk = bid - (E_ + V_);
            #pragma unroll
            for (int h = 0; h < 2; ++h) {
                int c = tid + h * 256;
                int j = c >> 1, p = c & 1;
                g_cw2[kk * E2_ + c] = cw[kk * E2_ + p * E_ + j];
            }
        } else {
            #pragma unroll
            for (int h = 0; h < 2; ++h) {
                int c = tid + h * 256;
                int j = c >> 1, p = c & 1;
                g_cb2[c] = cb[p * E_ + j];
            }
        }
        return;
    }
    bid -= NB_PREP;

    // ---- transpose dec -> g_decT[b][e][s] ----
    {
        __shared__ float tile[32][33];
        int s0 = (bid & 15) << 5;
        int e0 = ((bid >> 4) & 7) << 5;
        int b  = bid >> 7;
        int tx = tid & 31, ty = tid >> 5;
        #pragma unroll
        for (int i = 0; i < 32; i += 8)
            tile[ty + i][tx] = dec[((b << 9) + s0 + ty + i) * E_ + e0 + tx];
        __syncthreads();
        #pragma unroll
        for (int i = 0; i < 32; i += 8)
            g_decT[((b << 8) + e0 + ty + i) * HW_ + s0 + tx] = tile[tx][ty + i];
    }
}

// ---------------------------------------------------------------------------
// K1: conv split-k GEMM -> g_part[k]
// grid 384 = k(3) x b(16) x n-tile(8); 256 threads; thread tile 4m x 4n
// A[m][kk] = g_aT[b][ci][m+k-1] (zero-pad), B = g_cw2 slice for this k
// ---------------------------------------------------------------------------
__global__ __launch_bounds__(256) void k_conv4() {
    __shared__ __align__(16) float As[2][16][68];
    __shared__ __align__(16) float Bs[2][16][68];

    int bid = blockIdx.x;
    int nt  = bid & 7;
    int bb  = (bid >> 3) & 15;
    int k   = bid >> 7;                  // 0..2
    int n0  = nt << 6;
    int ksh = k - 1;                     // shift: As[kc][m] = aT[ci][m+ksh]

    int tid = threadIdx.x;
    int kcL = tid >> 4, qL = tid & 15;   // loader mapping (A and B)
    int mi  = tid >> 4, ni = tid & 15;   // compute mapping

    const float* aTb = g_aT + bb * (E_ * T_);
    const float* wB  = g_cw2 + (k * E_) * E2_ + n0;

    int mb = 4 * qL + 1 - k;             // write base m for A scatter

    // ---- prologue: chunk 0 (ci0 = 0) ----
    {
        float4 va = *(const float4*)&aTb[kcL * T_ + 4 * qL];
        float4 vb = *(const float4*)&wB[kcL * E2_ + 4 * qL];
        *(float4*)&Bs[0][kcL][4 * qL] = vb;
        float av[4] = {va.x, va.y, va.z, va.w};
        #pragma unroll
        for (int j = 0; j < 4; ++j) {
            int m = mb + j;
            if ((unsigned)m < 64u) As[0][kcL][m] = av[j];
        }
        if (k == 0 && qL == 0)  As[0][kcL][0]  = 0.f;
        if (k == 2 && qL == 15) As[0][kcL][63] = 0.f;
    }
    __syncthreads();

    ull acc[2][4];
    #pragma unroll
    for (int p = 0; p < 2; ++p)
        #pragma unroll
        for (int j = 0; j < 4; ++j) acc[p][j] = pack2(0.f, 0.f);

    float4 vaN, vbN;
    for (int ch = 0; ch < 16; ++ch) {
        int cur = ch & 1;
        if (ch < 15) {
            int ci0 = (ch + 1) << 4;
            vaN = *(const float4*)&aTb[(ci0 + kcL) * T_ + 4 * qL];
            vbN = *(const float4*)&wB[(ci0 + kcL) * E2_ + 4 * qL];
        }

        #pragma unroll
        for (int kc = 0; kc < 16; ++kc) {
            ulonglong2 av = *(const ulonglong2*)&As[cur][kc][4 * mi];
            float4     bv = *(const float4*)    &Bs[cur][kc][4 * ni];
            ull b0 = pack2(bv.x, bv.x);
            ull b1 = pack2(bv.y, bv.y);
            ull b2 = pack2(bv.z, bv.z);
            ull b3 = pack2(bv.w, bv.w);
            acc[0][0] = ffma2(av.x, b0, acc[0][0]);
            acc[0][1] = ffma2(av.x, b1, acc[0][1]);
            acc[0][2] = ffma2(av.x, b2, acc[0][2]);
            acc[0][3] = ffma2(av.x, b3, acc[0][3]);
            acc[1][0] = ffma2(av.y, b0, acc[1][0]);
            acc[1][1] = ffma2(av.y, b1, acc[1][1]);
            acc[1][2] = ffma2(av.y, b2, acc[1][2]);
            acc[1][3] = ffma2(av.y, b3, acc[1][3]);
        }

        if (ch < 15) {
            int nxt = cur ^ 1;
            *(float4*)&Bs[nxt][kcL][4 * qL] = vbN;
            float av[4] = {vaN.x, vaN.y, vaN.z, vaN.w};
            #pragma unroll
            for (int j = 0; j < 4; ++j) {
                int m = mb + j;
                if ((unsigned)m < 64u) As[nxt][kcL][m] = av[j];
            }
            if (k == 0 && qL == 0)  As[nxt][kcL][0]  = 0.f;
            if (k == 2 && qL == 15) As[nxt][kcL][63] = 0.f;
        }
        __syncthreads();
    }

    // ---- epilogue: write partials (float4 rows) ----
    float* pb = g_part + (size_t)k * BT_ * E2_ + ((bb << 6) + 4 * mi) * E2_ + n0 + 4 * ni;
    #pragma unroll
    for (int p = 0; p < 2; ++p) {
        float l0, h0, l1, h1, l2, h2, l3, h3;
        unpack2(acc[p][0], l0, h0);
        unpack2(acc[p][1], l1, h1);
        unpack2(acc[p][2], l2, h2);
        unpack2(acc[p][3], l3, h3);
        float* r0 = pb + (2 * p) * E2_;
        *(float4*)r0         = make_float4(l0, l1, l2, l3);
        *(float4*)(r0 + E2_) = make_float4(h0, h1, h2, h3);
    }
}

// ---------------------------------------------------------------------------
// K1b: reduce 3 partials + bias + GLU -> g_z
// grid 1024 rows, 256 threads; thread handles interleaved col pair (2j,2j+1)
// ---------------------------------------------------------------------------
__global__ __launch_bounds__(256) void k_glu() {
    int row = blockIdx.x, j = threadIdx.x;
    size_t off = (size_t)row * E2_ + 2 * j;
    float2 p0 = *(const float2*)&g_part[off];
    float2 p1 = *(const float2*)&g_part[off + (size_t)BT_ * E2_];
    float2 p2 = *(const float2*)&g_part[off + (size_t)2 * BT_ * E2_];
    float2 bb = *(const float2*)&g_cb2[2 * j];
    float za = p0.x + p1.x + p2.x + bb.x;
    float zb = p0.y + p1.y + p2.y + bb.y;
    g_z[row * E_ + j] = za / (1.f + expf(-zb));
}

// ---------------------------------------------------------------------------
// K2: fused h-projection + attention (writes g_a AND g_aT)
// grid 128 = 16 b * 8 t-tiles; 256 threads
// ---------------------------------------------------------------------------
__global__ __launch_bounds__(256) void k_attn2(const float* __restrict__ Wb) {
    __shared__ __align__(16) float zt [E_][8];
    __shared__ __align__(16) float qt [E_][8];
    __shared__ __align__(16) float sst[HW_][8];
    __shared__ float rsum[8];

    int b    = blockIdx.x >> 3;
    int t0   = (blockIdx.x & 7) << 3;
    int tid  = threadIdx.x;
    int lane = tid & 31;
    int wid  = tid >> 5;
    int row0 = (b << 6) + t0;

    // ---- phase 0a: z tile to smem ----
    #pragma unroll
    for (int r = 0; r < 8; ++r)
        zt[tid][r] = g_z[(row0 + r) * E_ + tid];
    __syncthreads();

    // ---- phase 0b: h = z @ W^T + Wb + s -> qt ----
    {
        ull hacc[4];
        #pragma unroll
        for (int p = 0; p < 4; ++p) hacc[p] = pack2(0.f, 0.f);

        #pragma unroll 8
        for (int i = 0; i < E_; ++i) {
            float wv = g_Wt[i * E_ + tid];
            ull wp = pack2(wv, wv);
            ulonglong2 z01 = *(const ulonglong2*)&zt[i][0];
            ulonglong2 z23 = *(const ulonglong2*)&zt[i][4];
            hacc[0] = ffma2(z01.x, wp, hacc[0]);
            hacc[1] = ffma2(z01.y, wp, hacc[1]);
            hacc[2] = ffma2(z23.x, wp, hacc[2]);
            hacc[3] = ffma2(z23.y, wp, hacc[3]);
        }
        float wb = Wb[tid];
        #pragma unroll
        for (int p = 0; p < 4; ++p) {
            float h0, h1; unpack2(hacc[p], h0, h1);
            int r = 2 * p;
            float q0 = h0 + wb + g_s[(row0 + r)     * E_ + tid];
            float q1 = h1 + wb + g_s[(row0 + r + 1) * E_ + tid];
            *(ull*)&qt[tid][r] = pack2(q0, q1);
        }
    }
    __syncthreads();

    // ---- phase 1: scores = h @ decT (thread owns s = tid, tid+256) ----
    {
        ull A0[4], A1[4];
        #pragma unroll
        for (int j = 0; j < 4; ++j) { A0[j] = pack2(0.f, 0.f); A1[j] = pack2(0.f, 0.f); }

        const float* kb = g_decT + ((size_t)b << 8) * HW_ + tid;
        #pragma unroll 8
        for (int e = 0; e < E_; ++e) {
            float k0 = kb[e * HW_];
            float k1 = kb[e * HW_ + 256];
            ull kp0 = pack2(k0, k0);
            ull kp1 = pack2(k1, k1);
            ulonglong2 q01 = *(const ulonglong2*)&qt[e][0];
            ulonglong2 q23 = *(const ulonglong2*)&qt[e][4];
            A0[0] = ffma2(q01.x, kp0, A0[0]);
            A0[1] = ffma2(q01.y, kp0, A0[1]);
            A0[2] = ffma2(q23.x, kp0, A0[2]);
            A0[3] = ffma2(q23.y, kp0, A0[3]);
            A1[0] = ffma2(q01.x, kp1, A1[0]);
            A1[1] = ffma2(q01.y, kp1, A1[1]);
            A1[2] = ffma2(q23.x, kp1, A1[2]);
            A1[3] = ffma2(q23.y, kp1, A1[3]);
        }
        ull* s0p = (ull*)&sst[tid][0];
        ull* s1p = (ull*)&sst[tid + 256][0];
        #pragma unroll
        for (int j = 0; j < 4; ++j) { s0p[j] = A0[j]; s1p[j] = A1[j]; }
    }
    __syncthreads();

    // ---- phase 2: softmax over s (warp wid handles t = wid) ----
    {
        int t = wid;
        float m = -1e30f;
        for (int s = lane; s < HW_; s += 32) m = fmaxf(m, sst[s][t]);
        #pragma unroll
        for (int off = 16; off; off >>= 1)
            m = fmaxf(m, __shfl_xor_sync(0xffffffffu, m, off));
        float sum = 0.f;
        for (int s = lane; s < HW_; s += 32) {
            float ev = expf(sst[s][t] - m);
            sst[s][t] = ev;
            sum += ev;
        }
        #pragma unroll
        for (int off = 16; off; off >>= 1)
            sum += __shfl_xor_sync(0xffffffffu, sum, off);
        if (lane == 0) rsum[t] = 1.f / sum;
    }
    __syncthreads();

    // ---- phase 3: c = (exp-scores @ res) * rsum; a = c + z ----
    {
        const float* resb = g_res + ((size_t)b * HW_) * E_;
        int e = tid;
        ull acc[4];
        #pragma unroll
        for (int p = 0; p < 4; ++p) acc[p] = pack2(0.f, 0.f);

        #pragma unroll 8
        for (int s = 0; s < HW_; ++s) {
            float rv = resb[s * E_ + e];
            ull rp = pack2(rv, rv);
            ulonglong2 a01 = *(const ulonglong2*)&sst[s][0];
            ulonglong2 a23 = *(const ulonglong2*)&sst[s][4];
            acc[0] = ffma2(a01.x, rp, acc[0]);
            acc[1] = ffma2(a01.y, rp, acc[1]);
            acc[2] = ffma2(a23.x, rp, acc[2]);
            acc[3] = ffma2(a23.y, rp, acc[3]);
        }

        float av8[8];
        #pragma unroll
        for (int p = 0; p < 4; ++p) {
            float c0, c1; unpack2(acc[p], c0, c1);
            int t = 2 * p;
            int idx = (row0 + t) * E_ + e;
            float v0 = c0 * rsum[t]     + zt[e][t];
            float v1 = c1 * rsum[t + 1] + zt[e][t + 1];
            g_a[idx]      = v0;
            g_a[idx + E_] = v1;
            av8[t] = v0; av8[t + 1] = v1;
        }
        // transposed copy for next conv: g_aT[b][e][t0..t0+7]
        float* atp = g_aT + b * (E_ * T_) + e * T_ + t0;
        *(float4*)atp       = make_float4(av8[0], av8[1], av8[2], av8[3]);
        *(float4*)(atp + 4) = make_float4(av8[4], av8[5], av8[6], av8[7]);
    }
}

// ---------------------------------------------------------------------------
// K3: logits = a @ Wo^T + Wo_b; log_softmax over V  -> out
// ---------------------------------------------------------------------------
__global__ __launch_bounds__(128) void k_logits(const float* __restrict__ Wob,
                                                float* __restrict__ out) {
    __shared__ __align__(16) float av4[4][E_];
    __shared__ float redm[4][4], reds[4][4];

    int row0 = blockIdx.x * 4;
    int v    = threadIdx.x;
    int lane = v & 31;
    int wid  = v >> 5;

    #pragma unroll
    for (int r = 0; r < 4; ++r) {
        av4[r][v]       = g_a[(row0 + r) * E_ + v];
        av4[r][v + 128] = g_a[(row0 + r) * E_ + v + 128];
    }
    __syncthreads();

    ull acc[4];
    #pragma unroll
    for (int r = 0; r < 4; ++r) acc[r] = pack2(0.f, 0.f);

    const ull* wop = (const ull*)g_Wop;
    #pragma unroll 4
    for (int ep = 0; ep < E_ / 2; ++ep) {
        ull wp = wop[ep * V_ + v];
        #pragma unroll
        for (int r = 0; r < 4; ++r)
            acc[r] = ffma2(((const ull*)av4[r])[ep], wp, acc[r]);
    }

    float lg[4], wb = Wob[v];
    #pragma unroll
    for (int r = 0; r < 4; ++r) {
        float lo, hi; unpack2(acc[r], lo, hi);
        lg[r] = lo + hi + wb;
    }

    float wm[4];
    #pragma unroll
    for (int r = 0; r < 4; ++r) {
        wm[r] = lg[r];
        #pragma unroll
        for (int off = 16; off; off >>= 1)
            wm[r] = fmaxf(wm[r], __shfl_xor_sync(0xffffffffu, wm[r], off));
    }
    if (lane == 0) {
        #pragma unroll
        for (int r = 0; r < 4; ++r) redm[r][wid] = wm[r];
    }
    __syncthreads();
    float bm[4];
    #pragma unroll
    for (int r = 0; r < 4; ++r)
        bm[r] = fmaxf(fmaxf(redm[r][0], redm[r][1]), fmaxf(redm[r][2], redm[r][3]));

    float ws[4];
    #pragma unroll
    for (int r = 0; r < 4; ++r) {
        ws[r] = expf(lg[r] - bm[r]);
        #pragma unroll
        for (int off = 16; off; off >>= 1)
            ws[r] += __shfl_xor_sync(0xffffffffu, ws[r], off);
    }
    if (lane == 0) {
        #pragma unroll
        for (int r = 0; r < 4; ++r) reds[r][wid] = ws[r];
    }
    __syncthreads();

    #pragma unroll
    for (int r = 0; r < 4; ++r) {
        float bs = reds[r][0] + reds[r][1] + reds[r][2] + reds[r][3];
        out[(row0 + r) * V_ + v] = lg[r] - bm[r] - logf(bs);
    }
}

// ---------------------------------------------------------------------------
// kernel_launch
// ---------------------------------------------------------------------------
extern "C" void kernel_launch(void* const* d_in, const int* in_sizes, int n_in,
                              void* d_out, int out_size) {
    int li = 2;
    for (int i = 0; i < n_in; ++i)
        if (in_sizes[i] == 1024) { li = i; break; }

    const float *enc, *dec, *emb, *cw, *cb, *Ww, *Wb, *Wo, *Wob;
    const int* labels;
    if (li == 2) {
        enc = (const float*)d_in[0]; dec = (const float*)d_in[1];
        labels = (const int*)d_in[2];
        emb = (const float*)d_in[3]; cw  = (const float*)d_in[4];
        cb  = (const float*)d_in[5]; Ww  = (const float*)d_in[6];
        Wb  = (const float*)d_in[7]; Wo  = (const float*)d_in[8];
        Wob = (const float*)d_in[9];
    } else {
        enc = (const float*)d_in[0]; dec = (const float*)d_in[1];
        emb = (const float*)d_in[2]; cw  = (const float*)d_in[3];
        cb  = (const float*)d_in[4]; Ww  = (const float*)d_in[5];
        Wb  = (const float*)d_in[6]; Wo  = (const float*)d_in[7];
        Wob = (const float*)d_in[8];
        labels = (const int*)d_in[9];
    }
    float* out = (float*)d_out;

    k_setup<<<NB_EMB + NB_RES + NB_PREP + NB_TR, 256>>>(labels, emb, enc, dec,
                                                        Ww, Wo, cw, cb);

    for (int l = 0; l < NBLK_; ++l) {
        k_conv4<<<384, 256>>>();
        k_glu  <<<BT_, 256>>>();
        k_attn2<<<128, 256>>>(Wb);
    }

    k_logits<<<BT_ / 4, 128>>>(Wob, out);
}

// round 7
// speedup vs baseline: 1.6830x; 1.1357x over previous
#include <cuda_runtime.h>
#include <math.h>

// ---------------------------------------------------------------------------
// Problem constants
// ---------------------------------------------------------------------------
#define B_    16
#define T_    64
#define HW_   512
#define E_    256
#define E2_   512
#define V_    128
#define BT_   1024   // B*T
#define NBLK_ 3

typedef unsigned long long ull;

// ---------------------------------------------------------------------------
// Scratch (device globals: no allocation allowed)
// ---------------------------------------------------------------------------
__device__ __align__(16) float g_s    [BT_ * E_];       // embed(labels), fixed
__device__ __align__(16) float g_a    [BT_ * E_];       // running activation (row-major)
__device__ __align__(16) float g_aT   [B_ * E_ * T_];   // a transposed [b][e][t]
__device__ __align__(16) float g_z    [BT_ * E_];       // GLU output
__device__ __align__(16) float g_h    [BT_ * E_];       // query rows
__device__ __align__(16) float g_res  [B_ * HW_ * E_];  // enc + dec
__device__ __align__(16) float g_Wt   [E_ * E_];        // W_w transposed: Wt[i][o]
__device__ __align__(16) float g_Wop  [E_ * V_];        // Wo interleaved e-pairs
__device__ __align__(16) float g_cw2  [3 * E_ * E2_];   // conv_w, GLU-interleaved cols
__device__ __align__(16) float g_cb2  [E2_];            // conv_b, interleaved
__device__ __align__(16) float g_decT [B_ * E_ * HW_];  // dec transposed [b][e][s]
__device__ __align__(16) float g_part [3 * BT_ * E2_];  // conv split-k partials
__device__ __align__(16) float g_alpha[BT_ * HW_];      // softmax probs
__device__ __align__(16) float g_cpart[4 * BT_ * E_];   // ctx split-s partials

// ---------------------------------------------------------------------------
// f32x2 packed math (sm_100+)
// ---------------------------------------------------------------------------
__device__ __forceinline__ ull pack2(float x, float y) {
    ull r; asm("mov.b64 %0, {%1,%2};" : "=l"(r) : "f"(x), "f"(y)); return r;
}
__device__ __forceinline__ void unpack2(ull v, float& x, float& y) {
    asm("mov.b64 {%0,%1}, %2;" : "=f"(x), "=f"(y) : "l"(v));
}
__device__ __forceinline__ ull ffma2(ull a, ull b, ull c) {
    ull d; asm("fma.rn.f32x2 %0, %1, %2, %3;" : "=l"(d) : "l"(a), "l"(b), "l"(c)); return d;
}

// ---------------------------------------------------------------------------
// K0: merged setup — embed | residual | weight-prep | dec transpose
// ---------------------------------------------------------------------------
#define NB_EMB  1024
#define NB_RES  2048
#define NB_PREP 1153
#define NB_TR   2048

__global__ __launch_bounds__(256) void k_setup(const int* __restrict__ labels,
                                               const float* __restrict__ emb,
                                               const float* __restrict__ enc,
                                               const float* __restrict__ dec,
                                               const float* __restrict__ Ww,
                                               const float* __restrict__ Wo,
                                               const float* __restrict__ cw,
                                               const float* __restrict__ cb) {
    int bid = blockIdx.x, tid = threadIdx.x;

    if (bid < NB_EMB) {
        int row = bid, e = tid;
        int lbl = labels[row];
        float v = emb[lbl * E_ + e];
        g_s[row * E_ + e] = v;
        g_a[row * E_ + e] = v;
        g_aT[(row >> 6) * (E_ * T_) + e * T_ + (row & 63)] = v;
        return;
    }
    bid -= NB_EMB;

    if (bid < NB_RES) {
        int i = bid * 256 + tid;
        float4 a = ((const float4*)enc)[i];
        float4 b = ((const float4*)dec)[i];
        float4 c;
        c.x = a.x + b.x; c.y = a.y + b.y; c.z = a.z + b.z; c.w = a.w + b.w;
        ((float4*)g_res)[i] = c;
        return;
    }
    bid -= NB_RES;

    if (bid < NB_PREP) {
        if (bid < E_) {
            g_Wt[tid * E_ + bid] = Ww[bid * E_ + tid];
        } else if (bid < E_ + V_) {
            int v = bid - E_;
            g_Wop[(tid >> 1) * (2 * V_) + 2 * v + (tid & 1)] = Wo[v * E_ + tid];
        } else if (bid < E_ + V_ + 3 * E_) {
            int kk = bid - (E_ + V_);
            #pragma unroll
            for (int h = 0; h < 2; ++h) {
                int c = tid + h * 256;
                int j = c >> 1, p = c & 1;
                g_cw2[kk * E2_ + c] = cw[kk * E2_ + p * E_ + j];
            }
        } else {
            #pragma unroll
            for (int h = 0; h < 2; ++h) {
                int c = tid + h * 256;
                int j = c >> 1, p = c & 1;
                g_cb2[c] = cb[p * E_ + j];
            }
        }
        return;
    }
    bid -= NB_PREP;

    // ---- transpose dec -> g_decT[b][e][s] ----
    {
        __shared__ float tile[32][33];
        int s0 = (bid & 15) << 5;
        int e0 = ((bid >> 4) & 7) << 5;
        int b  = bid >> 7;
        int tx = tid & 31, ty = tid >> 5;
        #pragma unroll
        for (int i = 0; i < 32; i += 8)
            tile[ty + i][tx] = dec[((b << 9) + s0 + ty + i) * E_ + e0 + tx];
        __syncthreads();
        #pragma unroll
        for (int i = 0; i < 32; i += 8)
            g_decT[((b << 8) + e0 + ty + i) * HW_ + s0 + tx] = tile[tx][ty + i];
    }
}

// ---------------------------------------------------------------------------
// K1: conv split-k GEMM -> g_part[k]
// grid 384 = k(3) x b(16) x n-tile(8); 256 threads; thread tile 4m x 4n
// ---------------------------------------------------------------------------
__global__ __launch_bounds__(256) void k_conv4() {
    __shared__ __align__(16) float As[2][16][68];
    __shared__ __align__(16) float Bs[2][16][68];

    int bid = blockIdx.x;
    int nt  = bid & 7;
    int bb  = (bid >> 3) & 15;
    int k   = bid >> 7;                  // 0..2
    int n0  = nt << 6;

    int tid = threadIdx.x;
    int kcL = tid >> 4, qL = tid & 15;
    int mi  = tid >> 4, ni = tid & 15;

    const float* aTb = g_aT + bb * (E_ * T_);
    const float* wB  = g_cw2 + (k * E_) * E2_ + n0;

    int mb = 4 * qL + 1 - k;

    {
        float4 va = *(const float4*)&aTb[kcL * T_ + 4 * qL];
        float4 vb = *(const float4*)&wB[kcL * E2_ + 4 * qL];
        *(float4*)&Bs[0][kcL][4 * qL] = vb;
        float av[4] = {va.x, va.y, va.z, va.w};
        #pragma unroll
        for (int j = 0; j < 4; ++j) {
            int m = mb + j;
            if ((unsigned)m < 64u) As[0][kcL][m] = av[j];
        }
        if (k == 0 && qL == 0)  As[0][kcL][0]  = 0.f;
        if (k == 2 && qL == 15) As[0][kcL][63] = 0.f;
    }
    __syncthreads();

    ull acc[2][4];
    #pragma unroll
    for (int p = 0; p < 2; ++p)
        #pragma unroll
        for (int j = 0; j < 4; ++j) acc[p][j] = pack2(0.f, 0.f);

    float4 vaN, vbN;
    for (int ch = 0; ch < 16; ++ch) {
        int cur = ch & 1;
        if (ch < 15) {
            int ci0 = (ch + 1) << 4;
            vaN = *(const float4*)&aTb[(ci0 + kcL) * T_ + 4 * qL];
            vbN = *(const float4*)&wB[(ci0 + kcL) * E2_ + 4 * qL];
        }

        #pragma unroll
        for (int kc = 0; kc < 16; ++kc) {
            ulonglong2 av = *(const ulonglong2*)&As[cur][kc][4 * mi];
            float4     bv = *(const float4*)    &Bs[cur][kc][4 * ni];
            ull b0 = pack2(bv.x, bv.x);
            ull b1 = pack2(bv.y, bv.y);
            ull b2 = pack2(bv.z, bv.z);
            ull b3 = pack2(bv.w, bv.w);
            acc[0][0] = ffma2(av.x, b0, acc[0][0]);
            acc[0][1] = ffma2(av.x, b1, acc[0][1]);
            acc[0][2] = ffma2(av.x, b2, acc[0][2]);
            acc[0][3] = ffma2(av.x, b3, acc[0][3]);
            acc[1][0] = ffma2(av.y, b0, acc[1][0]);
            acc[1][1] = ffma2(av.y, b1, acc[1][1]);
            acc[1][2] = ffma2(av.y, b2, acc[1][2]);
            acc[1][3] = ffma2(av.y, b3, acc[1][3]);
        }

        if (ch < 15) {
            int nxt = cur ^ 1;
            *(float4*)&Bs[nxt][kcL][4 * qL] = vbN;
            float av[4] = {vaN.x, vaN.y, vaN.z, vaN.w};
            #pragma unroll
            for (int j = 0; j < 4; ++j) {
                int m = mb + j;
                if ((unsigned)m < 64u) As[nxt][kcL][m] = av[j];
            }
            if (k == 0 && qL == 0)  As[nxt][kcL][0]  = 0.f;
            if (k == 2 && qL == 15) As[nxt][kcL][63] = 0.f;
        }
        __syncthreads();
    }

    float* pb = g_part + (size_t)k * BT_ * E2_ + ((bb << 6) + 4 * mi) * E2_ + n0 + 4 * ni;
    #pragma unroll
    for (int p = 0; p < 2; ++p) {
        float l0, h0, l1, h1, l2, h2, l3, h3;
        unpack2(acc[p][0], l0, h0);
        unpack2(acc[p][1], l1, h1);
        unpack2(acc[p][2], l2, h2);
        unpack2(acc[p][3], l3, h3);
        float* r0 = pb + (2 * p) * E2_;
        *(float4*)r0         = make_float4(l0, l1, l2, l3);
        *(float4*)(r0 + E2_) = make_float4(h0, h1, h2, h3);
    }
}

// ---------------------------------------------------------------------------
// K1b: reduce 3 partials + bias + GLU -> g_z
// ---------------------------------------------------------------------------
__global__ __launch_bounds__(256) void k_glu() {
    int row = blockIdx.x, j = threadIdx.x;
    size_t off = (size_t)row * E2_ + 2 * j;
    float2 p0 = *(const float2*)&g_part[off];
    float2 p1 = *(const float2*)&g_part[off + (size_t)BT_ * E2_];
    float2 p2 = *(const float2*)&g_part[off + (size_t)2 * BT_ * E2_];
    float2 bb = *(const float2*)&g_cb2[2 * j];
    float za = p0.x + p1.x + p2.x + bb.x;
    float zb = p0.y + p1.y + p2.y + bb.y;
    g_z[row * E_ + j] = za / (1.f + expf(-zb));
}

// ---------------------------------------------------------------------------
// K2a: h = z @ W^T + Wb + s -> g_h
// grid 512 = 128 row-tiles(8 rows) x 4 o-groups(64); 256 threads
// thread = (o in group, row-pair)
// ---------------------------------------------------------------------------
__global__ __launch_bounds__(256) void k_hproj(const float* __restrict__ Wb) {
    __shared__ __align__(16) float zt[E_][8];
    int bid  = blockIdx.x;
    int og   = bid & 3;
    int rw   = bid >> 2;
    int row0 = rw << 3;
    int o0   = og << 6;
    int tid  = threadIdx.x;

    #pragma unroll
    for (int r = 0; r < 8; ++r)
        zt[tid][r] = g_z[(row0 + r) * E_ + tid];
    __syncthreads();

    int o  = o0 + (tid & 63);
    int rp = tid >> 6;                    // row-pair 0..3

    ull acc = pack2(0.f, 0.f);
    #pragma unroll 8
    for (int i = 0; i < E_; ++i) {
        float wv = g_Wt[i * E_ + o];
        ull zp = *(const ull*)&zt[i][2 * rp];
        acc = ffma2(zp, pack2(wv, wv), acc);
    }

    float h0, h1; unpack2(acc, h0, h1);
    float wb = Wb[o];
    int r0 = row0 + 2 * rp;
    g_h[r0 * E_ + o]       = h0 + wb + g_s[r0 * E_ + o];
    g_h[(r0 + 1) * E_ + o] = h1 + wb + g_s[(r0 + 1) * E_ + o];
}

// ---------------------------------------------------------------------------
// K2b: scores + softmax -> g_alpha
// grid 1024 (one (b,t) row per CTA); 256 threads; thread owns s-pair
// ---------------------------------------------------------------------------
__global__ __launch_bounds__(256) void k_scores() {
    __shared__ __align__(16) float q[E_];
    __shared__ float red[16];

    int row  = blockIdx.x;
    int b    = row >> 6;
    int tid  = threadIdx.x;
    int lane = tid & 31;
    int wid  = tid >> 5;

    q[tid] = g_h[row * E_ + tid];
    __syncthreads();

    const float* kb = g_decT + ((size_t)b << 8) * HW_ + 2 * tid;
    ull acc = pack2(0.f, 0.f);
    #pragma unroll 8
    for (int e = 0; e < E_; ++e) {
        float2 kv = *(const float2*)&kb[e * HW_];
        float qv = q[e];
        acc = ffma2(pack2(kv.x, kv.y), pack2(qv, qv), acc);
    }
    float s0, s1; unpack2(acc, s0, s1);

    // block max
    float m = fmaxf(s0, s1);
    #pragma unroll
    for (int off = 16; off; off >>= 1)
        m = fmaxf(m, __shfl_xor_sync(0xffffffffu, m, off));
    if (lane == 0) red[wid] = m;
    __syncthreads();
    float M = red[0];
    #pragma unroll
    for (int w = 1; w < 8; ++w) M = fmaxf(M, red[w]);

    float e0 = expf(s0 - M), e1 = expf(s1 - M);
    float sum = e0 + e1;
    #pragma unroll
    for (int off = 16; off; off >>= 1)
        sum += __shfl_xor_sync(0xffffffffu, sum, off);
    if (lane == 0) red[8 + wid] = sum;
    __syncthreads();
    float tot = red[8];
    #pragma unroll
    for (int w = 1; w < 8; ++w) tot += red[8 + w];
    float inv = 1.f / tot;

    *(float2*)&g_alpha[(size_t)row * HW_ + 2 * tid] = make_float2(e0 * inv, e1 * inv);
}

// ---------------------------------------------------------------------------
// K2c: ctx partials: c_part[sc] = alpha[:, sc-chunk] @ res[sc-chunk]
// grid 512 = b(16) x t-tile(8) x s-chunk(4); 256 threads (thread = e)
// ---------------------------------------------------------------------------
__global__ __launch_bounds__(256) void k_ctx() {
    __shared__ __align__(16) float al[128][8];

    int bid  = blockIdx.x;
    int sc   = bid & 3;
    int tt   = (bid >> 2) & 7;
    int b    = bid >> 5;
    int sb   = sc << 7;
    int row0 = (b << 6) + (tt << 3);
    int tid  = threadIdx.x;
    int lane = tid & 31;
    int wid  = tid >> 5;

    // load alpha tile transposed: warp wid owns row (row0+wid)
    {
        float4 av = *(const float4*)&g_alpha[(size_t)(row0 + wid) * HW_ + sb + 4 * lane];
        al[4 * lane + 0][wid] = av.x;
        al[4 * lane + 1][wid] = av.y;
        al[4 * lane + 2][wid] = av.z;
        al[4 * lane + 3][wid] = av.w;
    }
    __syncthreads();

    const float* resb = g_res + ((size_t)b * HW_ + sb) * E_ + tid;
    ull acc[4];
    #pragma unroll
    for (int p = 0; p < 4; ++p) acc[p] = pack2(0.f, 0.f);

    #pragma unroll 8
    for (int s = 0; s < 128; ++s) {
        float rv = resb[(size_t)s * E_];
        ull rp = pack2(rv, rv);
        ulonglong2 a01 = *(const ulonglong2*)&al[s][0];
        ulonglong2 a23 = *(const ulonglong2*)&al[s][4];
        acc[0] = ffma2(a01.x, rp, acc[0]);
        acc[1] = ffma2(a01.y, rp, acc[1]);
        acc[2] = ffma2(a23.x, rp, acc[2]);
        acc[3] = ffma2(a23.y, rp, acc[3]);
    }

    float* cp = g_cpart + ((size_t)sc * BT_ + row0) * E_ + tid;
    #pragma unroll
    for (int p = 0; p < 4; ++p) {
        float c0, c1; unpack2(acc[p], c0, c1);
        cp[(2 * p) * E_]     = c0;
        cp[(2 * p + 1) * E_] = c1;
    }
}

// ---------------------------------------------------------------------------
// K2d: a = sum(c_part) + z  -> g_a, g_aT
// grid 128 = b(16) x t-tile(8); 256 threads (thread = e)
// ---------------------------------------------------------------------------
__global__ __launch_bounds__(256) void k_afin() {
    int bid  = blockIdx.x;
    int b    = bid >> 3;
    int t0   = (bid & 7) << 3;
    int row0 = (b << 6) + t0;
    int e    = threadIdx.x;

    float av8[8];
    #pragma unroll
    for (int r = 0; r < 8; ++r) {
        size_t o = (size_t)(row0 + r) * E_ + e;
        float c = g_cpart[o]
                + g_cpart[(size_t)BT_ * E_ + o]
                + g_cpart[(size_t)2 * BT_ * E_ + o]
                + g_cpart[(size_t)3 * BT_ * E_ + o];
        float v = c + g_z[o];
        g_a[o] = v;
        av8[r] = v;
    }
    float* atp = g_aT + b * (E_ * T_) + e * T_ + t0;
    *(float4*)atp       = make_float4(av8[0], av8[1], av8[2], av8[3]);
    *(float4*)(atp + 4) = make_float4(av8[4], av8[5], av8[6], av8[7]);
}

// ---------------------------------------------------------------------------
// K3: logits = a @ Wo^T + Wo_b; log_softmax over V  -> out
// ---------------------------------------------------------------------------
__global__ __launch_bounds__(128) void k_logits(const float* __restrict__ Wob,
                                                float* __restrict__ out) {
    __shared__ __align__(16) float av4[4][E_];
    __shared__ float redm[4][4], reds[4][4];

    int row0 = blockIdx.x * 4;
    int v    = threadIdx.x;
    int lane = v & 31;
    int wid  = v >> 5;

    #pragma unroll
    for (int r = 0; r < 4; ++r) {
        av4[r][v]       = g_a[(row0 + r) * E_ + v];
        av4[r][v + 128] = g_a[(row0 + r) * E_ + v + 128];
    }
    __syncthreads();

    ull acc[4];
    #pragma unroll
    for (int r = 0; r < 4; ++r) acc[r] = pack2(0.f, 0.f);

    const ull* wop = (const ull*)g_Wop;
    #pragma unroll 4
    for (int ep = 0; ep < E_ / 2; ++ep) {
        ull wp = wop[ep * V_ + v];
        #pragma unroll
        for (int r = 0; r < 4; ++r)
            acc[r] = ffma2(((const ull*)av4[r])[ep], wp, acc[r]);
    }

    float lg[4], wb = Wob[v];
    #pragma unroll
    for (int r = 0; r < 4; ++r) {
        float lo, hi; unpack2(acc[r], lo, hi);
        lg[r] = lo + hi + wb;
    }

    float wm[4];
    #pragma unroll
    for (int r = 0; r < 4; ++r) {
        wm[r] = lg[r];
        #pragma unroll
        for (int off = 16; off; off >>= 1)
            wm[r] = fmaxf(wm[r], __shfl_xor_sync(0xffffffffu, wm[r], off));
    }
    if (lane == 0) {
        #pragma unroll
        for (int r = 0; r < 4; ++r) redm[r][wid] = wm[r];
    }
    __syncthreads();
    float bm[4];
    #pragma unroll
    for (int r = 0; r < 4; ++r)
        bm[r] = fmaxf(fmaxf(redm[r][0], redm[r][1]), fmaxf(redm[r][2], redm[r][3]));

    float ws[4];
    #pragma unroll
    for (int r = 0; r < 4; ++r) {
        ws[r] = expf(lg[r] - bm[r]);
        #pragma unroll
        for (int off = 16; off; off >>= 1)
            ws[r] += __shfl_xor_sync(0xffffffffu, ws[r], off);
    }
    if (lane == 0) {
        #pragma unroll
        for (int r = 0; r < 4; ++r) reds[r][wid] = ws[r];
    }
    __syncthreads();

    #pragma unroll
    for (int r = 0; r < 4; ++r) {
        float bs = reds[r][0] + reds[r][1] + reds[r][2] + reds[r][3];
        out[(row0 + r) * V_ + v] = lg[r] - bm[r] - logf(bs);
    }
}

// ---------------------------------------------------------------------------
// kernel_launch
// ---------------------------------------------------------------------------
extern "C" void kernel_launch(void* const* d_in, const int* in_sizes, int n_in,
                              void* d_out, int out_size) {
    int li = 2;
    for (int i = 0; i < n_in; ++i)
        if (in_sizes[i] == 1024) { li = i; break; }

    const float *enc, *dec, *emb, *cw, *cb, *Ww, *Wb, *Wo, *Wob;
    const int* labels;
    if (li == 2) {
        enc = (const float*)d_in[0]; dec = (const float*)d_in[1];
        labels = (const int*)d_in[2];
        emb = (const float*)d_in[3]; cw  = (const float*)d_in[4];
        cb  = (const float*)d_in[5]; Ww  = (const float*)d_in[6];
        Wb  = (const float*)d_in[7]; Wo  = (const float*)d_in[8];
        Wob = (const float*)d_in[9];
    } else {
        enc = (const float*)d_in[0]; dec = (const float*)d_in[1];
        emb = (const float*)d_in[2]; cw  = (const float*)d_in[3];
        cb  = (const float*)d_in[4]; Ww  = (const float*)d_in[5];
        Wb  = (const float*)d_in[6]; Wo  = (const float*)d_in[7];
        Wob = (const float*)d_in[8];
        labels = (const int*)d_in[9];
    }
    float* out = (float*)d_out;

    k_setup<<<NB_EMB + NB_RES + NB_PREP + NB_TR, 256>>>(labels, emb, enc, dec,
                                                        Ww, Wo, cw, cb);

    for (int l = 0; l < NBLK_; ++l) {
        k_conv4 <<<384, 256>>>();
        k_glu   <<<BT_, 256>>>();
        k_hproj <<<512, 256>>>(Wb);
        k_scores<<<BT_, 256>>>();
        k_ctx   <<<512, 256>>>();
        k_afin  <<<128, 256>>>();
    }

    k_logits<<<BT_ / 4, 128>>>(Wob, out);
}

// round 8
// speedup vs baseline: 1.7273x; 1.0263x over previous
#include <cuda_runtime.h>
#include <math.h>

// ---------------------------------------------------------------------------
// Problem constants
// ---------------------------------------------------------------------------
#define B_    16
#define T_    64
#define HW_   512
#define E_    256
#define E2_   512
#define V_    128
#define BT_   1024   // B*T
#define NBLK_ 3

typedef unsigned long long ull;

// ---------------------------------------------------------------------------
// Scratch (device globals: no allocation allowed)
// ---------------------------------------------------------------------------
__device__ __align__(16) float g_s    [BT_ * E_];       // embed(labels), fixed
__device__ __align__(16) float g_a    [BT_ * E_];       // running activation (row-major)
__device__ __align__(16) float g_aT   [B_ * E_ * T_];   // a transposed [b][e][t]
__device__ __align__(16) float g_z    [BT_ * E_];       // GLU output
__device__ __align__(16) float g_h    [BT_ * E_];       // query rows
__device__ __align__(16) float g_res  [B_ * HW_ * E_];  // enc + dec
__device__ __align__(16) float g_Wt   [E_ * E_];        // W_w transposed: Wt[i][o]
__device__ __align__(16) float g_Wop  [E_ * V_];        // Wo interleaved e-pairs
__device__ __align__(16) float g_cw2  [3 * E_ * E2_];   // conv_w, GLU-interleaved cols
__device__ __align__(16) float g_cb2  [E2_];            // conv_b, interleaved
__device__ __align__(16) float g_decT [B_ * E_ * HW_];  // dec transposed [b][e][s]
__device__ __align__(16) float g_part [3 * BT_ * E2_];  // conv split-k partials
__device__ __align__(16) float g_alpha[BT_ * HW_];      // softmax probs
__device__ __align__(16) float g_cpart[4 * BT_ * E_];   // ctx split-s partials

// ---------------------------------------------------------------------------
// f32x2 packed math (sm_100+)
// ---------------------------------------------------------------------------
__device__ __forceinline__ ull pack2(float x, float y) {
    ull r; asm("mov.b64 %0, {%1,%2};" : "=l"(r) : "f"(x), "f"(y)); return r;
}
__device__ __forceinline__ void unpack2(ull v, float& x, float& y) {
    asm("mov.b64 {%0,%1}, %2;" : "=f"(x), "=f"(y) : "l"(v));
}
__device__ __forceinline__ ull ffma2(ull a, ull b, ull c) {
    ull d; asm("fma.rn.f32x2 %0, %1, %2, %3;" : "=l"(d) : "l"(a), "l"(b), "l"(c)); return d;
}

// ---------------------------------------------------------------------------
// K0: merged setup — embed | residual | weight-prep | dec transpose
// ---------------------------------------------------------------------------
#define NB_EMB  1024
#define NB_RES  2048
#define NB_PREP 1153
#define NB_TR   2048

__global__ __launch_bounds__(256) void k_setup(const int* __restrict__ labels,
                                               const float* __restrict__ emb,
                                               const float* __restrict__ enc,
                                               const float* __restrict__ dec,
                                               const float* __restrict__ Ww,
                                               const float* __restrict__ Wo,
                                               const float* __restrict__ cw,
                                               const float* __restrict__ cb) {
    int bid = blockIdx.x, tid = threadIdx.x;

    if (bid < NB_EMB) {
        int row = bid, e = tid;
        int lbl = labels[row];
        float v = emb[lbl * E_ + e];
        g_s[row * E_ + e] = v;
        g_a[row * E_ + e] = v;
        g_aT[(row >> 6) * (E_ * T_) + e * T_ + (row & 63)] = v;
        return;
    }
    bid -= NB_EMB;

    if (bid < NB_RES) {
        int i = bid * 256 + tid;
        float4 a = ((const float4*)enc)[i];
        float4 b = ((const float4*)dec)[i];
        float4 c;
        c.x = a.x + b.x; c.y = a.y + b.y; c.z = a.z + b.z; c.w = a.w + b.w;
        ((float4*)g_res)[i] = c;
        return;
    }
    bid -= NB_RES;

    if (bid < NB_PREP) {
        if (bid < E_) {
            g_Wt[tid * E_ + bid] = Ww[bid * E_ + tid];
        } else if (bid < E_ + V_) {
            int v = bid - E_;
            g_Wop[(tid >> 1) * (2 * V_) + 2 * v + (tid & 1)] = Wo[v * E_ + tid];
        } else if (bid < E_ + V_ + 3 * E_) {
            int kk = bid - (E_ + V_);
            #pragma unroll
            for (int h = 0; h < 2; ++h) {
                int c = tid + h * 256;
                int j = c >> 1, p = c & 1;
                g_cw2[kk * E2_ + c] = cw[kk * E2_ + p * E_ + j];
            }
        } else {
            #pragma unroll
            for (int h = 0; h < 2; ++h) {
                int c = tid + h * 256;
                int j = c >> 1, p = c & 1;
                g_cb2[c] = cb[p * E_ + j];
            }
        }
        return;
    }
    bid -= NB_PREP;

    // ---- transpose dec -> g_decT[b][e][s] ----
    {
        __shared__ float tile[32][33];
        int s0 = (bid & 15) << 5;
        int e0 = ((bid >> 4) & 7) << 5;
        int b  = bid >> 7;
        int tx = tid & 31, ty = tid >> 5;
        #pragma unroll
        for (int i = 0; i < 32; i += 8)
            tile[ty + i][tx] = dec[((b << 9) + s0 + ty + i) * E_ + e0 + tx];
        __syncthreads();
        #pragma unroll
        for (int i = 0; i < 32; i += 8)
            g_decT[((b << 8) + e0 + ty + i) * HW_ + s0 + tx] = tile[tx][ty + i];
    }
}

// ---------------------------------------------------------------------------
// K1: conv split-k GEMM -> g_part[k]
// grid 384 = k(3) x b(16) x n-tile(8); 256 threads; thread tile 4m x 4n
// ---------------------------------------------------------------------------
__global__ __launch_bounds__(256) void k_conv4() {
    __shared__ __align__(16) float As[2][16][68];
    __shared__ __align__(16) float Bs[2][16][68];

    int bid = blockIdx.x;
    int nt  = bid & 7;
    int bb  = (bid >> 3) & 15;
    int k   = bid >> 7;                  // 0..2
    int n0  = nt << 6;

    int tid = threadIdx.x;
    int kcL = tid >> 4, qL = tid & 15;
    int mi  = tid >> 4, ni = tid & 15;

    const float* aTb = g_aT + bb * (E_ * T_);
    const float* wB  = g_cw2 + (k * E_) * E2_ + n0;

    int mb = 4 * qL + 1 - k;

    {
        float4 va = *(const float4*)&aTb[kcL * T_ + 4 * qL];
        float4 vb = *(const float4*)&wB[kcL * E2_ + 4 * qL];
        *(float4*)&Bs[0][kcL][4 * qL] = vb;
        float av[4] = {va.x, va.y, va.z, va.w};
        #pragma unroll
        for (int j = 0; j < 4; ++j) {
            int m = mb + j;
            if ((unsigned)m < 64u) As[0][kcL][m] = av[j];
        }
        if (k == 0 && qL == 0)  As[0][kcL][0]  = 0.f;
        if (k == 2 && qL == 15) As[0][kcL][63] = 0.f;
    }
    __syncthreads();

    ull acc[2][4];
    #pragma unroll
    for (int p = 0; p < 2; ++p)
        #pragma unroll
        for (int j = 0; j < 4; ++j) acc[p][j] = pack2(0.f, 0.f);

    float4 vaN, vbN;
    for (int ch = 0; ch < 16; ++ch) {
        int cur = ch & 1;
        if (ch < 15) {
            int ci0 = (ch + 1) << 4;
            vaN = *(const float4*)&aTb[(ci0 + kcL) * T_ + 4 * qL];
            vbN = *(const float4*)&wB[(ci0 + kcL) * E2_ + 4 * qL];
        }

        #pragma unroll
        for (int kc = 0; kc < 16; ++kc) {
            ulonglong2 av = *(const ulonglong2*)&As[cur][kc][4 * mi];
            float4     bv = *(const float4*)    &Bs[cur][kc][4 * ni];
            ull b0 = pack2(bv.x, bv.x);
            ull b1 = pack2(bv.y, bv.y);
            ull b2 = pack2(bv.z, bv.z);
            ull b3 = pack2(bv.w, bv.w);
            acc[0][0] = ffma2(av.x, b0, acc[0][0]);
            acc[0][1] = ffma2(av.x, b1, acc[0][1]);
            acc[0][2] = ffma2(av.x, b2, acc[0][2]);
            acc[0][3] = ffma2(av.x, b3, acc[0][3]);
            acc[1][0] = ffma2(av.y, b0, acc[1][0]);
            acc[1][1] = ffma2(av.y, b1, acc[1][1]);
            acc[1][2] = ffma2(av.y, b2, acc[1][2]);
            acc[1][3] = ffma2(av.y, b3, acc[1][3]);
        }

        if (ch < 15) {
            int nxt = cur ^ 1;
            *(float4*)&Bs[nxt][kcL][4 * qL] = vbN;
            float av[4] = {vaN.x, vaN.y, vaN.z, vaN.w};
            #pragma unroll
            for (int j = 0; j < 4; ++j) {
                int m = mb + j;
                if ((unsigned)m < 64u) As[nxt][kcL][m] = av[j];
            }
            if (k == 0 && qL == 0)  As[nxt][kcL][0]  = 0.f;
            if (k == 2 && qL == 15) As[nxt][kcL][63] = 0.f;
        }
        __syncthreads();
    }

    float* pb = g_part + (size_t)k * BT_ * E2_ + ((bb << 6) + 4 * mi) * E2_ + n0 + 4 * ni;
    #pragma unroll
    for (int p = 0; p < 2; ++p) {
        float l0, h0, l1, h1, l2, h2, l3, h3;
        unpack2(acc[p][0], l0, h0);
        unpack2(acc[p][1], l1, h1);
        unpack2(acc[p][2], l2, h2);
        unpack2(acc[p][3], l3, h3);
        float* r0 = pb + (2 * p) * E2_;
        *(float4*)r0         = make_float4(l0, l1, l2, l3);
        *(float4*)(r0 + E2_) = make_float4(h0, h1, h2, h3);
    }
}

// ---------------------------------------------------------------------------
// K1b: reduce 3 partials + bias + GLU -> g_z
// ---------------------------------------------------------------------------
__global__ __launch_bounds__(256) void k_glu() {
    int row = blockIdx.x, j = threadIdx.x;
    size_t off = (size_t)row * E2_ + 2 * j;
    float2 p0 = *(const float2*)&g_part[off];
    float2 p1 = *(const float2*)&g_part[off + (size_t)BT_ * E2_];
    float2 p2 = *(const float2*)&g_part[off + (size_t)2 * BT_ * E2_];
    float2 bb = *(const float2*)&g_cb2[2 * j];
    float za = p0.x + p1.x + p2.x + bb.x;
    float zb = p0.y + p1.y + p2.y + bb.y;
    g_z[row * E_ + j] = za / (1.f + expf(-zb));
}

// ---------------------------------------------------------------------------
// K2a: h = z @ W^T + Wb + s -> g_h
// grid 512 = 128 row-tiles(8 rows) x 4 o-groups(64); 128 threads
// thread = (o in group of 64, rpg in {0,1} covering row-pairs 2rpg,2rpg+1)
// ---------------------------------------------------------------------------
__global__ __launch_bounds__(128) void k_hproj(const float* __restrict__ Wb) {
    __shared__ __align__(16) float zt[E_][8];
    int bid  = blockIdx.x;
    int og   = bid & 3;
    int rw   = bid >> 2;
    int row0 = rw << 3;
    int o0   = og << 6;
    int tid  = threadIdx.x;

    #pragma unroll
    for (int r = 0; r < 8; ++r) {
        zt[tid][r]       = g_z[(row0 + r) * E_ + tid];
        zt[tid + 128][r] = g_z[(row0 + r) * E_ + tid + 128];
    }
    __syncthreads();

    int oo  = tid & 63;
    int rpg = tid >> 6;                  // 0 or 1
    int o   = o0 + oo;

    ull acc0 = pack2(0.f, 0.f), acc1 = pack2(0.f, 0.f);
    #pragma unroll 8
    for (int i = 0; i < E_; ++i) {
        float wv = g_Wt[i * E_ + o];
        ull wp = pack2(wv, wv);
        ulonglong2 zp = *(const ulonglong2*)&zt[i][4 * rpg];
        acc0 = ffma2(zp.x, wp, acc0);
        acc1 = ffma2(zp.y, wp, acc1);
    }

    float wb = Wb[o];
    float h0, h1, h2, h3;
    unpack2(acc0, h0, h1);
    unpack2(acc1, h2, h3);
    int r0 = row0 + 4 * rpg;
    g_h[(r0)     * E_ + o] = h0 + wb + g_s[(r0)     * E_ + o];
    g_h[(r0 + 1) * E_ + o] = h1 + wb + g_s[(r0 + 1) * E_ + o];
    g_h[(r0 + 2) * E_ + o] = h2 + wb + g_s[(r0 + 2) * E_ + o];
    g_h[(r0 + 3) * E_ + o] = h3 + wb + g_s[(r0 + 3) * E_ + o];
}

// ---------------------------------------------------------------------------
// K2b: scores + softmax -> g_alpha
// grid 256 (4 t-rows per CTA); 256 threads; thread owns s = tid, tid+256
// accumulates 4 t's per s as 2 f32x2 pairs
// ---------------------------------------------------------------------------
__global__ __launch_bounds__(256) void k_scores() {
    __shared__ __align__(16) float qt [E_][4];
    __shared__ __align__(16) float sst[HW_][4];
    __shared__ float redM[4][2], redS[4][2], Iv[4], Mv[4];

    int row0 = blockIdx.x << 2;          // 4 rows, never crosses b (64 | 4)
    int b    = row0 >> 6;
    int tid  = threadIdx.x;
    int lane = tid & 31;
    int w    = tid >> 5;

    #pragma unroll
    for (int r = 0; r < 4; ++r)
        qt[tid][r] = g_h[(row0 + r) * E_ + tid];
    __syncthreads();

    const float* kb = g_decT + ((size_t)b << 8) * HW_ + tid;
    ull a00 = pack2(0.f, 0.f), a01 = a00, a10 = a00, a11 = a00;
    #pragma unroll 8
    for (int e = 0; e < E_; ++e) {
        float k0 = kb[e * HW_];
        float k1 = kb[e * HW_ + 256];
        ull kp0 = pack2(k0, k0);
        ull kp1 = pack2(k1, k1);
        ulonglong2 qp = *(const ulonglong2*)&qt[e][0];
        a00 = ffma2(qp.x, kp0, a00);
        a01 = ffma2(qp.y, kp0, a01);
        a10 = ffma2(qp.x, kp1, a10);
        a11 = ffma2(qp.y, kp1, a11);
    }
    {
        ull* p0 = (ull*)&sst[tid][0];
        p0[0] = a00; p0[1] = a01;
        ull* p1 = (ull*)&sst[tid + 256][0];
        p1[0] = a10; p1[1] = a11;
    }
    __syncthreads();

    // softmax: warp w handles t = w&3, s-half = w>>2
    int t  = w & 3;
    int sh = (w >> 2) << 8;
    float m = -1e30f;
    #pragma unroll
    for (int k = 0; k < 8; ++k)
        m = fmaxf(m, sst[sh + k * 32 + lane][t]);
    #pragma unroll
    for (int off = 16; off; off >>= 1)
        m = fmaxf(m, __shfl_xor_sync(0xffffffffu, m, off));
    if (lane == 0) redM[t][w >> 2] = m;
    __syncthreads();
    float M = fmaxf(redM[t][0], redM[t][1]);

    float sum = 0.f;
    #pragma unroll
    for (int k = 0; k < 8; ++k) {
        int s = sh + k * 32 + lane;
        float ev = expf(sst[s][t] - M);
        sst[s][t] = ev;
        sum += ev;
    }
    #pragma unroll
    for (int off = 16; off; off >>= 1)
        sum += __shfl_xor_sync(0xffffffffu, sum, off);
    if (lane == 0) redS[t][w >> 2] = sum;
    __syncthreads();
    if (tid < 4) Iv[tid] = 1.f / (redS[tid][0] + redS[tid][1]);
    __syncthreads();

    #pragma unroll
    for (int r = 0; r < 4; ++r) {
        float inv = Iv[r];
        size_t o = (size_t)(row0 + r) * HW_;
        g_alpha[o + tid]       = sst[tid][r]       * inv;
        g_alpha[o + tid + 256] = sst[tid + 256][r] * inv;
    }
}

// ---------------------------------------------------------------------------
// K2c: ctx partials: c_part[sc] = alpha[:, sc-chunk] @ res[sc-chunk]
// grid 512 = b(16) x t-tile(8) x s-chunk(4); 256 threads (thread = e)
// ---------------------------------------------------------------------------
__global__ __launch_bounds__(256) void k_ctx() {
    __shared__ __align__(16) float al[128][8];

    int bid  = blockIdx.x;
    int sc   = bid & 3;
    int tt   = (bid >> 2) & 7;
    int b    = bid >> 5;
    int sb   = sc << 7;
    int row0 = (b << 6) + (tt << 3);
    int tid  = threadIdx.x;
    int lane = tid & 31;
    int wid  = tid >> 5;

    {
        float4 av = *(const float4*)&g_alpha[(size_t)(row0 + wid) * HW_ + sb + 4 * lane];
        al[4 * lane + 0][wid] = av.x;
        al[4 * lane + 1][wid] = av.y;
        al[4 * lane + 2][wid] = av.z;
        al[4 * lane + 3][wid] = av.w;
    }
    __syncthreads();

    const float* resb = g_res + ((size_t)b * HW_ + sb) * E_ + tid;
    ull acc[4];
    #pragma unroll
    for (int p = 0; p < 4; ++p) acc[p] = pack2(0.f, 0.f);

    #pragma unroll 8
    for (int s = 0; s < 128; ++s) {
        float rv = resb[(size_t)s * E_];
        ull rp = pack2(rv, rv);
        ulonglong2 a01 = *(const ulonglong2*)&al[s][0];
        ulonglong2 a23 = *(const ulonglong2*)&al[s][4];
        acc[0] = ffma2(a01.x, rp, acc[0]);
        acc[1] = ffma2(a01.y, rp, acc[1]);
        acc[2] = ffma2(a23.x, rp, acc[2]);
        acc[3] = ffma2(a23.y, rp, acc[3]);
    }

    float* cp = g_cpart + ((size_t)sc * BT_ + row0) * E_ + tid;
    #pragma unroll
    for (int p = 0; p < 4; ++p) {
        float c0, c1; unpack2(acc[p], c0, c1);
        cp[(2 * p) * E_]     = c0;
        cp[(2 * p + 1) * E_] = c1;
    }
}

// ---------------------------------------------------------------------------
// K2d: a = sum(c_part) + z  -> g_a, g_aT
// ---------------------------------------------------------------------------
__global__ __launch_bounds__(256) void k_afin() {
    int bid  = blockIdx.x;
    int b    = bid >> 3;
    int t0   = (bid & 7) << 3;
    int row0 = (b << 6) + t0;
    int e    = threadIdx.x;

    float av8[8];
    #pragma unroll
    for (int r = 0; r < 8; ++r) {
        size_t o = (size_t)(row0 + r) * E_ + e;
        float c = g_cpart[o]
                + g_cpart[(size_t)BT_ * E_ + o]
                + g_cpart[(size_t)2 * BT_ * E_ + o]
                + g_cpart[(size_t)3 * BT_ * E_ + o];
        float v = c + g_z[o];
        g_a[o] = v;
        av8[r] = v;
    }
    float* atp = g_aT + b * (E_ * T_) + e * T_ + t0;
    *(float4*)atp       = make_float4(av8[0], av8[1], av8[2], av8[3]);
    *(float4*)(atp + 4) = make_float4(av8[4], av8[5], av8[6], av8[7]);
}

// ---------------------------------------------------------------------------
// K3: logits = a @ Wo^T + Wo_b; log_softmax over V  -> out
// ---------------------------------------------------------------------------
__global__ __launch_bounds__(128) void k_logits(const float* __restrict__ Wob,
                                                float* __restrict__ out) {
    __shared__ __align__(16) float av4[4][E_];
    __shared__ float redm[4][4], reds[4][4];

    int row0 = blockIdx.x * 4;
    int v    = threadIdx.x;
    int lane = v & 31;
    int wid  = v >> 5;

    #pragma unroll
    for (int r = 0; r < 4; ++r) {
        av4[r][v]       = g_a[(row0 + r) * E_ + v];
        av4[r][v + 128] = g_a[(row0 + r) * E_ + v + 128];
    }
    __syncthreads();

    ull acc[4];
    #pragma unroll
    for (int r = 0; r < 4; ++r) acc[r] = pack2(0.f, 0.f);

    const ull* wop = (const ull*)g_Wop;
    #pragma unroll 4
    for (int ep = 0; ep < E_ / 2; ++ep) {
        ull wp = wop[ep * V_ + v];
        #pragma unroll
        for (int r = 0; r < 4; ++r)
            acc[r] = ffma2(((const ull*)av4[r])[ep], wp, acc[r]);
    }

    float lg[4], wb = Wob[v];
    #pragma unroll
    for (int r = 0; r < 4; ++r) {
        float lo, hi; unpack2(acc[r], lo, hi);
        lg[r] = lo + hi + wb;
    }

    float wm[4];
    #pragma unroll
    for (int r = 0; r < 4; ++r) {
        wm[r] = lg[r];
        #pragma unroll
        for (int off = 16; off; off >>= 1)
            wm[r] = fmaxf(wm[r], __shfl_xor_sync(0xffffffffu, wm[r], off));
    }
    if (lane == 0) {
        #pragma unroll
        for (int r = 0; r < 4; ++r) redm[r][wid] = wm[r];
    }
    __syncthreads();
    float bm[4];
    #pragma unroll
    for (int r = 0; r < 4; ++r)
        bm[r] = fmaxf(fmaxf(redm[r][0], redm[r][1]), fmaxf(redm[r][2], redm[r][3]));

    float ws[4];
    #pragma unroll
    for (int r = 0; r < 4; ++r) {
        ws[r] = expf(lg[r] - bm[r]);
        #pragma unroll
        for (int off = 16; off; off >>= 1)
            ws[r] += __shfl_xor_sync(0xffffffffu, ws[r], off);
    }
    if (lane == 0) {
        #pragma unroll
        for (int r = 0; r < 4; ++r) reds[r][wid] = ws[r];
    }
    __syncthreads();

    #pragma unroll
    for (int r = 0; r < 4; ++r) {
        float bs = reds[r][0] + reds[r][1] + reds[r][2] + reds[r][3];
        out[(row0 + r) * V_ + v] = lg[r] - bm[r] - logf(bs);
    }
}

// ---------------------------------------------------------------------------
// kernel_launch
// ---------------------------------------------------------------------------
extern "C" void kernel_launch(void* const* d_in, const int* in_sizes, int n_in,
                              void* d_out, int out_size) {
    int li = 2;
    for (int i = 0; i < n_in; ++i)
        if (in_sizes[i] == 1024) { li = i; break; }

    const float *enc, *dec, *emb, *cw, *cb, *Ww, *Wb, *Wo, *Wob;
    const int* labels;
    if (li == 2) {
        enc = (const float*)d_in[0]; dec = (const float*)d_in[1];
        labels = (const int*)d_in[2];
        emb = (const float*)d_in[3]; cw  = (const float*)d_in[4];
        cb  = (const float*)d_in[5]; Ww  = (const float*)d_in[6];
        Wb  = (const float*)d_in[7]; Wo  = (const float*)d_in[8];
        Wob = (const float*)d_in[9];
    } else {
        enc = (const float*)d_in[0]; dec = (const float*)d_in[1];
        emb = (const float*)d_in[2]; cw  = (const float*)d_in[3];
        cb  = (const float*)d_in[4]; Ww  = (const float*)d_in[5];
        Wb  = (const float*)d_in[6]; Wo  = (const float*)d_in[7];
        Wob = (const float*)d_in[8];
        labels = (const int*)d_in[9];
    }
    float* out = (float*)d_out;

    k_setup<<<NB_EMB + NB_RES + NB_PREP + NB_TR, 256>>>(labels, emb, enc, dec,
                                                        Ww, Wo, cw, cb);

    for (int l = 0; l < NBLK_; ++l) {
        k_conv4 <<<384, 256>>>();
        k_glu   <<<BT_, 256>>>();
        k_hproj <<<512, 128>>>(Wb);
        k_scores<<<256, 256>>>();
        k_ctx   <<<512, 256>>>();
        k_afin  <<<128, 256>>>();
    }

    k_logits<<<BT_ / 4, 128>>>(Wob, out);
}

// round 9
// speedup vs baseline: 1.8715x; 1.0835x over previous
#include <cuda_runtime.h>
#include <math.h>

// ---------------------------------------------------------------------------
// Problem constants
// ---------------------------------------------------------------------------
#define B_    16
#define T_    64
#define HW_   512
#define E_    256
#define E2_   512
#define V_    128
#define BT_   1024   // B*T
#define NBLK_ 3

typedef unsigned long long ull;

// ---------------------------------------------------------------------------
// Scratch (device globals: no allocation allowed)
// ---------------------------------------------------------------------------
__device__ __align__(16) float g_s    [BT_ * E_];       // embed(labels), fixed
__device__ __align__(16) float g_a    [BT_ * E_];       // running activation (row-major)
__device__ __align__(16) float g_aT   [B_ * E_ * T_];   // a transposed [b][e][t]
__device__ __align__(16) float g_z    [BT_ * E_];       // GLU output
__device__ __align__(16) float g_h    [BT_ * E_];       // query rows
__device__ __align__(16) float g_res  [B_ * HW_ * E_];  // enc + dec
__device__ __align__(16) float g_Wt   [E_ * E_];        // W_w transposed: Wt[i][o]
__device__ __align__(16) float g_Wop  [E_ * V_];        // Wo interleaved e-pairs
__device__ __align__(16) float g_cw2  [3 * E_ * E2_];   // conv_w, GLU-interleaved cols
__device__ __align__(16) float g_cb2  [E2_];            // conv_b, interleaved
__device__ __align__(16) float g_decT [B_ * E_ * HW_];  // dec transposed [b][e][s]
__device__ __align__(16) float g_part [3 * BT_ * E2_];  // conv split-k partials
__device__ __align__(16) float g_hpart[2 * BT_ * E_];   // hproj split-k partials
__device__ __align__(16) float g_alpha[BT_ * HW_];      // softmax probs
__device__ __align__(16) float g_cpart[4 * BT_ * E_];   // ctx split-s partials

// ---------------------------------------------------------------------------
// f32x2 packed math (sm_100+)
// ---------------------------------------------------------------------------
__device__ __forceinline__ ull pack2(float x, float y) {
    ull r; asm("mov.b64 %0, {%1,%2};" : "=l"(r) : "f"(x), "f"(y)); return r;
}
__device__ __forceinline__ void unpack2(ull v, float& x, float& y) {
    asm("mov.b64 {%0,%1}, %2;" : "=f"(x), "=f"(y) : "l"(v));
}
__device__ __forceinline__ ull ffma2(ull a, ull b, ull c) {
    ull d; asm("fma.rn.f32x2 %0, %1, %2, %3;" : "=l"(d) : "l"(a), "l"(b), "l"(c)); return d;
}

// ---------------------------------------------------------------------------
// K0: merged setup — embed | residual | weight-prep | dec transpose
// ---------------------------------------------------------------------------
#define NB_EMB  1024
#define NB_RES  2048
#define NB_PREP 1153
#define NB_TR   2048

__global__ __launch_bounds__(256) void k_setup(const int* __restrict__ labels,
                                               const float* __restrict__ emb,
                                               const float* __restrict__ enc,
                                               const float* __restrict__ dec,
                                               const float* __restrict__ Ww,
                                               const float* __restrict__ Wo,
                                               const float* __restrict__ cw,
                                               const float* __restrict__ cb) {
    int bid = blockIdx.x, tid = threadIdx.x;

    if (bid < NB_EMB) {
        int row = bid, e = tid;
        int lbl = labels[row];
        float v = emb[lbl * E_ + e];
        g_s[row * E_ + e] = v;
        g_a[row * E_ + e] = v;
        g_aT[(row >> 6) * (E_ * T_) + e * T_ + (row & 63)] = v;
        return;
    }
    bid -= NB_EMB;

    if (bid < NB_RES) {
        int i = bid * 256 + tid;
        float4 a = ((const float4*)enc)[i];
        float4 b = ((const float4*)dec)[i];
        float4 c;
        c.x = a.x + b.x; c.y = a.y + b.y; c.z = a.z + b.z; c.w = a.w + b.w;
        ((float4*)g_res)[i] = c;
        return;
    }
    bid -= NB_RES;

    if (bid < NB_PREP) {
        if (bid < E_) {
            g_Wt[tid * E_ + bid] = Ww[bid * E_ + tid];
        } else if (bid < E_ + V_) {
            int v = bid - E_;
            g_Wop[(tid >> 1) * (2 * V_) + 2 * v + (tid & 1)] = Wo[v * E_ + tid];
        } else if (bid < E_ + V_ + 3 * E_) {
            int kk = bid - (E_ + V_);
            #pragma unroll
            for (int h = 0; h < 2; ++h) {
                int c = tid + h * 256;
                int j = c >> 1, p = c & 1;
                g_cw2[kk * E2_ + c] = cw[kk * E2_ + p * E_ + j];
            }
        } else {
            #pragma unroll
            for (int h = 0; h < 2; ++h) {
                int c = tid + h * 256;
                int j = c >> 1, p = c & 1;
                g_cb2[c] = cb[p * E_ + j];
            }
        }
        return;
    }
    bid -= NB_PREP;

    // ---- transpose dec -> g_decT[b][e][s] ----
    {
        __shared__ float tile[32][33];
        int s0 = (bid & 15) << 5;
        int e0 = ((bid >> 4) & 7) << 5;
        int b  = bid >> 7;
        int tx = tid & 31, ty = tid >> 5;
        #pragma unroll
        for (int i = 0; i < 32; i += 8)
            tile[ty + i][tx] = dec[((b << 9) + s0 + ty + i) * E_ + e0 + tx];
        __syncthreads();
        #pragma unroll
        for (int i = 0; i < 32; i += 8)
            g_decT[((b << 8) + e0 + ty + i) * HW_ + s0 + tx] = tile[tx][ty + i];
    }
}

// ---------------------------------------------------------------------------
// K1: conv split-k GEMM -> g_part[k]
// grid 384 = k(3) x b(16) x n-tile(8); 256 threads; thread tile 4m x 4n
// ---------------------------------------------------------------------------
__global__ __launch_bounds__(256) void k_conv4() {
    __shared__ __align__(16) float As[2][16][68];
    __shared__ __align__(16) float Bs[2][16][68];

    int bid = blockIdx.x;
    int nt  = bid & 7;
    int bb  = (bid >> 3) & 15;
    int k   = bid >> 7;                  // 0..2
    int n0  = nt << 6;

    int tid = threadIdx.x;
    int kcL = tid >> 4, qL = tid & 15;
    int mi  = tid >> 4, ni = tid & 15;

    const float* aTb = g_aT + bb * (E_ * T_);
    const float* wB  = g_cw2 + (k * E_) * E2_ + n0;

    int mb = 4 * qL + 1 - k;

    {
        float4 va = *(const float4*)&aTb[kcL * T_ + 4 * qL];
        float4 vb = *(const float4*)&wB[kcL * E2_ + 4 * qL];
        *(float4*)&Bs[0][kcL][4 * qL] = vb;
        float av[4] = {va.x, va.y, va.z, va.w};
        #pragma unroll
        for (int j = 0; j < 4; ++j) {
            int m = mb + j;
            if ((unsigned)m < 64u) As[0][kcL][m] = av[j];
        }
        if (k == 0 && qL == 0)  As[0][kcL][0]  = 0.f;
        if (k == 2 && qL == 15) As[0][kcL][63] = 0.f;
    }
    __syncthreads();

    ull acc[2][4];
    #pragma unroll
    for (int p = 0; p < 2; ++p)
        #pragma unroll
        for (int j = 0; j < 4; ++j) acc[p][j] = pack2(0.f, 0.f);

    float4 vaN, vbN;
    for (int ch = 0; ch < 16; ++ch) {
        int cur = ch & 1;
        if (ch < 15) {
            int ci0 = (ch + 1) << 4;
            vaN = *(const float4*)&aTb[(ci0 + kcL) * T_ + 4 * qL];
            vbN = *(const float4*)&wB[(ci0 + kcL) * E2_ + 4 * qL];
        }

        #pragma unroll
        for (int kc = 0; kc < 16; ++kc) {
            ulonglong2 av = *(const ulonglong2*)&As[cur][kc][4 * mi];
            float4     bv = *(const float4*)    &Bs[cur][kc][4 * ni];
            ull b0 = pack2(bv.x, bv.x);
            ull b1 = pack2(bv.y, bv.y);
            ull b2 = pack2(bv.z, bv.z);
            ull b3 = pack2(bv.w, bv.w);
            acc[0][0] = ffma2(av.x, b0, acc[0][0]);
            acc[0][1] = ffma2(av.x, b1, acc[0][1]);
            acc[0][2] = ffma2(av.x, b2, acc[0][2]);
            acc[0][3] = ffma2(av.x, b3, acc[0][3]);
            acc[1][0] = ffma2(av.y, b0, acc[1][0]);
            acc[1][1] = ffma2(av.y, b1, acc[1][1]);
            acc[1][2] = ffma2(av.y, b2, acc[1][2]);
            acc[1][3] = ffma2(av.y, b3, acc[1][3]);
        }

        if (ch < 15) {
            int nxt = cur ^ 1;
            *(float4*)&Bs[nxt][kcL][4 * qL] = vbN;
            float av[4] = {vaN.x, vaN.y, vaN.z, vaN.w};
            #pragma unroll
            for (int j = 0; j < 4; ++j) {
                int m = mb + j;
                if ((unsigned)m < 64u) As[nxt][kcL][m] = av[j];
            }
            if (k == 0 && qL == 0)  As[nxt][kcL][0]  = 0.f;
            if (k == 2 && qL == 15) As[nxt][kcL][63] = 0.f;
        }
        __syncthreads();
    }

    float* pb = g_part + (size_t)k * BT_ * E2_ + ((bb << 6) + 4 * mi) * E2_ + n0 + 4 * ni;
    #pragma unroll
    for (int p = 0; p < 2; ++p) {
        float l0, h0, l1, h1, l2, h2, l3, h3;
        unpack2(acc[p][0], l0, h0);
        unpack2(acc[p][1], l1, h1);
        unpack2(acc[p][2], l2, h2);
        unpack2(acc[p][3], l3, h3);
        float* r0 = pb + (2 * p) * E2_;
        *(float4*)r0         = make_float4(l0, l1, l2, l3);
        *(float4*)(r0 + E2_) = make_float4(h0, h1, h2, h3);
    }
}

// ---------------------------------------------------------------------------
// K1b: reduce 3 partials + bias + GLU -> g_z
// ---------------------------------------------------------------------------
__global__ __launch_bounds__(256) void k_glu() {
    int row = blockIdx.x, j = threadIdx.x;
    size_t off = (size_t)row * E2_ + 2 * j;
    float2 p0 = *(const float2*)&g_part[off];
    float2 p1 = *(const float2*)&g_part[off + (size_t)BT_ * E2_];
    float2 p2 = *(const float2*)&g_part[off + (size_t)2 * BT_ * E2_];
    float2 bb = *(const float2*)&g_cb2[2 * j];
    float za = p0.x + p1.x + p2.x + bb.x;
    float zb = p0.y + p1.y + p2.y + bb.y;
    g_z[row * E_ + j] = za / (1.f + expf(-zb));
}

// ---------------------------------------------------------------------------
// K2a: h partials: split-K GEMM  C[row][o] += z[row][k-half] @ Wt[k-half][o]
// grid 128 = kh(2) x row-tile(16 of 64) x o-tile(4 of 64); 256 threads
// thread tile 4m x 4n (m pairs packed f32x2) — same skeleton as k_conv4
// ---------------------------------------------------------------------------
__global__ __launch_bounds__(256) void k_hgemm() {
    __shared__ __align__(16) float As[2][16][68];
    __shared__ __align__(16) float Bs[2][16][68];

    int bid  = blockIdx.x;
    int ot   = bid & 3;
    int rt   = (bid >> 2) & 15;
    int kh   = bid >> 6;                 // 0/1
    int row0 = rt << 6;
    int o0   = ot << 6;
    int k0   = kh << 7;

    int tid = threadIdx.x;
    int mA  = tid >> 2, qA = tid & 3;    // A loader: row mA, i-group 4*qA
    int kcL = tid >> 4, qL = tid & 15;   // B loader
    int mi  = tid >> 4, ni = tid & 15;   // compute mapping

    const float* zb = g_z + row0 * E_ + k0;
    const float* wB = g_Wt + k0 * E_ + o0;

    // ---- prologue: chunk 0 ----
    {
        float4 va = *(const float4*)&zb[mA * E_ + 4 * qA];
        As[0][4 * qA + 0][mA] = va.x;
        As[0][4 * qA + 1][mA] = va.y;
        As[0][4 * qA + 2][mA] = va.z;
        As[0][4 * qA + 3][mA] = va.w;
        float4 vb = *(const float4*)&wB[kcL * E_ + 4 * qL];
        *(float4*)&Bs[0][kcL][4 * qL] = vb;
    }
    __syncthreads();

    ull acc[2][4];
    #pragma unroll
    for (int p = 0; p < 2; ++p)
        #pragma unroll
        for (int j = 0; j < 4; ++j) acc[p][j] = pack2(0.f, 0.f);

    float4 vaN, vbN;
    for (int ch = 0; ch < 8; ++ch) {
        int cur = ch & 1;
        if (ch < 7) {
            int ci0 = (ch + 1) << 4;
            vaN = *(const float4*)&zb[mA * E_ + ci0 + 4 * qA];
            vbN = *(const float4*)&wB[(ci0 + kcL) * E_ + 4 * qL];
        }

        #pragma unroll
        for (int kc = 0; kc < 16; ++kc) {
            ulonglong2 av = *(const ulonglong2*)&As[cur][kc][4 * mi];
            float4     bv = *(const float4*)    &Bs[cur][kc][4 * ni];
            ull b0 = pack2(bv.x, bv.x);
            ull b1 = pack2(bv.y, bv.y);
            ull b2 = pack2(bv.z, bv.z);
            ull b3 = pack2(bv.w, bv.w);
            acc[0][0] = ffma2(av.x, b0, acc[0][0]);
            acc[0][1] = ffma2(av.x, b1, acc[0][1]);
            acc[0][2] = ffma2(av.x, b2, acc[0][2]);
            acc[0][3] = ffma2(av.x, b3, acc[0][3]);
            acc[1][0] = ffma2(av.y, b0, acc[1][0]);
            acc[1][1] = ffma2(av.y, b1, acc[1][1]);
            acc[1][2] = ffma2(av.y, b2, acc[1][2]);
            acc[1][3] = ffma2(av.y, b3, acc[1][3]);
        }

        if (ch < 7) {
            int nxt = cur ^ 1;
            As[nxt][4 * qA + 0][mA] = vaN.x;
            As[nxt][4 * qA + 1][mA] = vaN.y;
            As[nxt][4 * qA + 2][mA] = vaN.z;
            As[nxt][4 * qA + 3][mA] = vaN.w;
            *(float4*)&Bs[nxt][kcL][4 * qL] = vbN;
        }
        __syncthreads();
    }

    float* pb = g_hpart + (size_t)kh * BT_ * E_ + (row0 + 4 * mi) * E_ + o0 + 4 * ni;
    #pragma unroll
    for (int p = 0; p < 2; ++p) {
        float l0, h0, l1, h1, l2, h2, l3, h3;
        unpack2(acc[p][0], l0, h0);
        unpack2(acc[p][1], l1, h1);
        unpack2(acc[p][2], l2, h2);
        unpack2(acc[p][3], l3, h3);
        float* r0 = pb + (2 * p) * E_;
        *(float4*)r0        = make_float4(l0, l1, l2, l3);
        *(float4*)(r0 + E_) = make_float4(h0, h1, h2, h3);
    }
}

// ---------------------------------------------------------------------------
// K2a': h = p0 + p1 + Wb + s -> g_h  (float4, memory-bound)
// grid 256, 256 threads
// ---------------------------------------------------------------------------
__global__ __launch_bounds__(256) void k_hfin(const float* __restrict__ Wb) {
    int i = blockIdx.x * 256 + threadIdx.x;          // float4 index
    float4 p0 = ((const float4*)g_hpart)[i];
    float4 p1 = ((const float4*)g_hpart)[i + BT_ * E_ / 4];
    float4 sv = ((const float4*)g_s)[i];
    int o = (i * 4) & (E_ - 1);
    float4 wb = *(const float4*)&Wb[o];
    float4 h;
    h.x = p0.x + p1.x + wb.x + sv.x;
    h.y = p0.y + p1.y + wb.y + sv.y;
    h.z = p0.z + p1.z + wb.z + sv.z;
    h.w = p0.w + p1.w + wb.w + sv.w;
    ((float4*)g_h)[i] = h;
}

// ---------------------------------------------------------------------------
// K2b: scores + softmax -> g_alpha
// grid 128 (8 t-rows per CTA); 512 threads; thread owns s = tid
// accumulates 8 t's per s as 4 f32x2 pairs
// ---------------------------------------------------------------------------
__global__ __launch_bounds__(512) void k_scores() {
    __shared__ __align__(16) float qt [E_][8];
    __shared__ __align__(16) float sst[HW_][8];
    __shared__ float redM[8][2], redS[8][2], Iv[8];

    int row0 = blockIdx.x << 3;          // 8 rows, never crosses b (64 | 8)
    int b    = row0 >> 6;
    int tid  = threadIdx.x;
    int lane = tid & 31;
    int w    = tid >> 5;                 // 0..15

    {
        int e  = tid & 255;
        int rh = tid >> 8;               // 0/1
        #pragma unroll
        for (int j = 0; j < 4; ++j)
            qt[e][rh * 4 + j] = g_h[(row0 + rh * 4 + j) * E_ + e];
    }
    __syncthreads();

    const float* kb = g_decT + ((size_t)b << 8) * HW_ + tid;
    ull A[4];
    #pragma unroll
    for (int j = 0; j < 4; ++j) A[j] = pack2(0.f, 0.f);

    #pragma unroll 8
    for (int e = 0; e < E_; ++e) {
        float kv = kb[e * HW_];
        ull kp = pack2(kv, kv);
        ulonglong2 q01 = *(const ulonglong2*)&qt[e][0];
        ulonglong2 q23 = *(const ulonglong2*)&qt[e][4];
        A[0] = ffma2(q01.x, kp, A[0]);
        A[1] = ffma2(q01.y, kp, A[1]);
        A[2] = ffma2(q23.x, kp, A[2]);
        A[3] = ffma2(q23.y, kp, A[3]);
    }
    {
        ull* sp = (ull*)&sst[tid][0];
        #pragma unroll
        for (int j = 0; j < 4; ++j) sp[j] = A[j];
    }
    __syncthreads();

    // softmax: warp w handles t = w&7, s-half = w>>3 (256 s each)
    int t  = w & 7;
    int sh = (w >> 3) << 8;
    float m = -1e30f;
    #pragma unroll
    for (int k = 0; k < 8; ++k)
        m = fmaxf(m, sst[sh + k * 32 + lane][t]);
    #pragma unroll
    for (int off = 16; off; off >>= 1)
        m = fmaxf(m, __shfl_xor_sync(0xffffffffu, m, off));
    if (lane == 0) redM[t][w >> 3] = m;
    __syncthreads();
    float M = fmaxf(redM[t][0], redM[t][1]);

    float sum = 0.f;
    #pragma unroll
    for (int k = 0; k < 8; ++k) {
        int s = sh + k * 32 + lane;
        float ev = expf(sst[s][t] - M);
        sst[s][t] = ev;
        sum += ev;
    }
    #pragma unroll
    for (int off = 16; off; off >>= 1)
        sum += __shfl_xor_sync(0xffffffffu, sum, off);
    if (lane == 0) redS[t][w >> 3] = sum;
    __syncthreads();
    if (tid < 8) Iv[tid] = 1.f / (redS[tid][0] + redS[tid][1]);
    __syncthreads();

    #pragma unroll
    for (int r = 0; r < 8; ++r)
        g_alpha[(size_t)(row0 + r) * HW_ + tid] = sst[tid][r] * Iv[r];
}

// ---------------------------------------------------------------------------
// K2c: ctx partials: c_part[sc] = alpha[:, sc-chunk] @ res[sc-chunk]
// grid 512 = b(16) x t-tile(8) x s-chunk(4); 256 threads (thread = e)
// ---------------------------------------------------------------------------
__global__ __launch_bounds__(256) void k_ctx() {
    __shared__ __align__(16) float al[128][8];

    int bid  = blockIdx.x;
    int sc   = bid & 3;
    int tt   = (bid >> 2) & 7;
    int b    = bid >> 5;
    int sb   = sc << 7;
    int row0 = (b << 6) + (tt << 3);
    int tid  = threadIdx.x;
    int lane = tid & 31;
    int wid  = tid >> 5;

    {
        float4 av = *(const float4*)&g_alpha[(size_t)(row0 + wid) * HW_ + sb + 4 * lane];
        al[4 * lane + 0][wid] = av.x;
        al[4 * lane + 1][wid] = av.y;
        al[4 * lane + 2][wid] = av.z;
        al[4 * lane + 3][wid] = av.w;
    }
    __syncthreads();

    const float* resb = g_res + ((size_t)b * HW_ + sb) * E_ + tid;
    ull acc[4];
    #pragma unroll
    for (int p = 0; p < 4; ++p) acc[p] = pack2(0.f, 0.f);

    #pragma unroll 8
    for (int s = 0; s < 128; ++s) {
        float rv = resb[(size_t)s * E_];
        ull rp = pack2(rv, rv);
        ulonglong2 a01 = *(const ulonglong2*)&al[s][0];
        ulonglong2 a23 = *(const ulonglong2*)&al[s][4];
        acc[0] = ffma2(a01.x, rp, acc[0]);
        acc[1] = ffma2(a01.y, rp, acc[1]);
        acc[2] = ffma2(a23.x, rp, acc[2]);
        acc[3] = ffma2(a23.y, rp, acc[3]);
    }

    float* cp = g_cpart + ((size_t)sc * BT_ + row0) * E_ + tid;
    #pragma unroll
    for (int p = 0; p < 4; ++p) {
        float c0, c1; unpack2(acc[p], c0, c1);
        cp[(2 * p) * E_]     = c0;
        cp[(2 * p + 1) * E_] = c1;
    }
}

// ---------------------------------------------------------------------------
// K2d: a = sum(c_part) + z  -> g_a, g_aT
// ---------------------------------------------------------------------------
__global__ __launch_bounds__(256) void k_afin() {
    int bid  = blockIdx.x;
    int b    = bid >> 3;
    int t0   = (bid & 7) << 3;
    int row0 = (b << 6) + t0;
    int e    = threadIdx.x;

    float av8[8];
    #pragma unroll
    for (int r = 0; r < 8; ++r) {
        size_t o = (size_t)(row0 + r) * E_ + e;
        float c = g_cpart[o]
                + g_cpart[(size_t)BT_ * E_ + o]
                + g_cpart[(size_t)2 * BT_ * E_ + o]
                + g_cpart[(size_t)3 * BT_ * E_ + o];
        float v = c + g_z[o];
        g_a[o] = v;
        av8[r] = v;
    }
    float* atp = g_aT + b * (E_ * T_) + e * T_ + t0;
    *(float4*)atp       = make_float4(av8[0], av8[1], av8[2], av8[3]);
    *(float4*)(atp + 4) = make_float4(av8[4], av8[5], av8[6], av8[7]);
}

// ---------------------------------------------------------------------------
// K3: logits = a @ Wo^T + Wo_b; log_softmax over V  -> out
// ---------------------------------------------------------------------------
__global__ __launch_bounds__(128) void k_logits(const float* __restrict__ Wob,
                                                float* __restrict__ out) {
    __shared__ __align__(16) float av4[4][E_];
    __shared__ float redm[4][4], reds[4][4];

    int row0 = blockIdx.x * 4;
    int v    = threadIdx.x;
    int lane = v & 31;
    int wid  = v >> 5;

    #pragma unroll
    for (int r = 0; r < 4; ++r) {
        av4[r][v]       = g_a[(row0 + r) * E_ + v];
        av4[r][v + 128] = g_a[(row0 + r) * E_ + v + 128];
    }
    __syncthreads();

    ull acc[4];
    #pragma unroll
    for (int r = 0; r < 4; ++r) acc[r] = pack2(0.f, 0.f);

    const ull* wop = (const ull*)g_Wop;
    #pragma unroll 4
    for (int ep = 0; ep < E_ / 2; ++ep) {
        ull wp = wop[ep * V_ + v];
        #pragma unroll
        for (int r = 0; r < 4; ++r)
            acc[r] = ffma2(((const ull*)av4[r])[ep], wp, acc[r]);
    }

    float lg[4], wb = Wob[v];
    #pragma unroll
    for (int r = 0; r < 4; ++r) {
        float lo, hi; unpack2(acc[r], lo, hi);
        lg[r] = lo + hi + wb;
    }

    float wm[4];
    #pragma unroll
    for (int r = 0; r < 4; ++r) {
        wm[r] = lg[r];
        #pragma unroll
        for (int off = 16; off; off >>= 1)
            wm[r] = fmaxf(wm[r], __shfl_xor_sync(0xffffffffu, wm[r], off));
    }
    if (lane == 0) {
        #pragma unroll
        for (int r = 0; r < 4; ++r) redm[r][wid] = wm[r];
    }
    __syncthreads();
    float bm[4];
    #pragma unroll
    for (int r = 0; r < 4; ++r)
        bm[r] = fmaxf(fmaxf(redm[r][0], redm[r][1]), fmaxf(redm[r][2], redm[r][3]));

    float ws[4];
    #pragma unroll
    for (int r = 0; r < 4; ++r) {
        ws[r] = expf(lg[r] - bm[r]);
        #pragma unroll
        for (int off = 16; off; off >>= 1)
            ws[r] += __shfl_xor_sync(0xffffffffu, ws[r], off);
    }
    if (lane == 0) {
        #pragma unroll
        for (int r = 0; r < 4; ++r) reds[r][wid] = ws[r];
    }
    __syncthreads();

    #pragma unroll
    for (int r = 0; r < 4; ++r) {
        float bs = reds[r][0] + reds[r][1] + reds[r][2] + reds[r][3];
        out[(row0 + r) * V_ + v] = lg[r] - bm[r] - logf(bs);
    }
}

// ---------------------------------------------------------------------------
// kernel_launch
// ---------------------------------------------------------------------------
extern "C" void kernel_launch(void* const* d_in, const int* in_sizes, int n_in,
                              void* d_out, int out_size) {
    int li = 2;
    for (int i = 0; i < n_in; ++i)
        if (in_sizes[i] == 1024) { li = i; break; }

    const float *enc, *dec, *emb, *cw, *cb, *Ww, *Wb, *Wo, *Wob;
    const int* labels;
    if (li == 2) {
        enc = (const float*)d_in[0]; dec = (const float*)d_in[1];
        labels = (const int*)d_in[2];
        emb = (const float*)d_in[3]; cw  = (const float*)d_in[4];
        cb  = (const float*)d_in[5]; Ww  = (const float*)d_in[6];
        Wb  = (const float*)d_in[7]; Wo  = (const float*)d_in[8];
        Wob = (const float*)d_in[9];
    } else {
        enc = (const float*)d_in[0]; dec = (const float*)d_in[1];
        emb = (const float*)d_in[2]; cw  = (const float*)d_in[3];
        cb  = (const float*)d_in[4]; Ww  = (const float*)d_in[5];
        Wb  = (const float*)d_in[6]; Wo  = (const float*)d_in[7];
        Wob = (const float*)d_in[8];
        labels = (const int*)d_in[9];
    }
    float* out = (float*)d_out;

    k_setup<<<NB_EMB + NB_RES + NB_PREP + NB_TR, 256>>>(labels, emb, enc, dec,
                                                        Ww, Wo, cw, cb);

    for (int l = 0; l < NBLK_; ++l) {
        k_conv4 <<<384, 256>>>();
        k_glu   <<<BT_, 256>>>();
        k_hgemm <<<128, 256>>>();
        k_hfin  <<<256, 256>>>(Wb);
        k_scores<<<128, 512>>>();
        k_ctx   <<<512, 256>>>();
        k_afin  <<<128, 256>>>();
    }

    k_logits<<<BT_ / 4, 128>>>(Wob, out);
}

// round 10
// speedup vs baseline: 1.8866x; 1.0081x over previous
#include <cuda_runtime.h>
#include <math.h>

// ---------------------------------------------------------------------------
// Problem constants
// ---------------------------------------------------------------------------
#define B_    16
#define T_    64
#define HW_   512
#define E_    256
#define E2_   512
#define V_    128
#define BT_   1024   // B*T
#define NBLK_ 3

typedef unsigned long long ull;

// ---------------------------------------------------------------------------
// Scratch (device globals: no allocation allowed)
// ---------------------------------------------------------------------------
__device__ __align__(16) float g_s    [BT_ * E_];       // embed(labels), fixed
__device__ __align__(16) float g_a    [BT_ * E_];       // running activation (row-major)
__device__ __align__(16) float g_aT   [B_ * E_ * T_];   // a transposed [b][e][t]
__device__ __align__(16) float g_z    [BT_ * E_];       // GLU output
__device__ __align__(16) float g_res  [B_ * HW_ * E_];  // enc + dec
__device__ __align__(16) float g_Wt   [E_ * E_];        // W_w transposed: Wt[i][o]
__device__ __align__(16) float g_Wop  [E_ * V_];        // Wo interleaved e-pairs
__device__ __align__(16) float g_cw2  [3 * E_ * E2_];   // conv_w, GLU-interleaved cols
__device__ __align__(16) float g_cb2  [E2_];            // conv_b, interleaved
__device__ __align__(16) float g_decT [B_ * E_ * HW_];  // dec transposed [b][e][s]
__device__ __align__(16) float g_part [6 * BT_ * E2_];  // conv split-k partials
__device__ __align__(16) float g_hpart[4 * BT_ * E_];   // hproj split-k partials
__device__ __align__(16) float g_alpha[BT_ * HW_];      // softmax probs
__device__ __align__(16) float g_cpart[4 * BT_ * E_];   // ctx split-s partials

// ---------------------------------------------------------------------------
// f32x2 packed math (sm_100+)
// ---------------------------------------------------------------------------
__device__ __forceinline__ ull pack2(float x, float y) {
    ull r; asm("mov.b64 %0, {%1,%2};" : "=l"(r) : "f"(x), "f"(y)); return r;
}
__device__ __forceinline__ void unpack2(ull v, float& x, float& y) {
    asm("mov.b64 {%0,%1}, %2;" : "=f"(x), "=f"(y) : "l"(v));
}
__device__ __forceinline__ ull ffma2(ull a, ull b, ull c) {
    ull d; asm("fma.rn.f32x2 %0, %1, %2, %3;" : "=l"(d) : "l"(a), "l"(b), "l"(c)); return d;
}

// ---------------------------------------------------------------------------
// K0: merged setup — embed | residual | weight-prep | dec transpose
// ---------------------------------------------------------------------------
#define NB_EMB  1024
#define NB_RES  2048
#define NB_PREP 1153
#define NB_TR   2048

__global__ __launch_bounds__(256) void k_setup(const int* __restrict__ labels,
                                               const float* __restrict__ emb,
                                               const float* __restrict__ enc,
                                               const float* __restrict__ dec,
                                               const float* __restrict__ Ww,
                                               const float* __restrict__ Wo,
                                               const float* __restrict__ cw,
                                               const float* __restrict__ cb) {
    int bid = blockIdx.x, tid = threadIdx.x;

    if (bid < NB_EMB) {
        int row = bid, e = tid;
        int lbl = labels[row];
        float v = emb[lbl * E_ + e];
        g_s[row * E_ + e] = v;
        g_a[row * E_ + e] = v;
        g_aT[(row >> 6) * (E_ * T_) + e * T_ + (row & 63)] = v;
        return;
    }
    bid -= NB_EMB;

    if (bid < NB_RES) {
        int i = bid * 256 + tid;
        float4 a = ((const float4*)enc)[i];
        float4 b = ((const float4*)dec)[i];
        float4 c;
        c.x = a.x + b.x; c.y = a.y + b.y; c.z = a.z + b.z; c.w = a.w + b.w;
        ((float4*)g_res)[i] = c;
        return;
    }
    bid -= NB_RES;

    if (bid < NB_PREP) {
        if (bid < E_) {
            g_Wt[tid * E_ + bid] = Ww[bid * E_ + tid];
        } else if (bid < E_ + V_) {
            int v = bid - E_;
            g_Wop[(tid >> 1) * (2 * V_) + 2 * v + (tid & 1)] = Wo[v * E_ + tid];
        } else if (bid < E_ + V_ + 3 * E_) {
            int kk = bid - (E_ + V_);
            #pragma unroll
            for (int h = 0; h < 2; ++h) {
                int c = tid + h * 256;
                int j = c >> 1, p = c & 1;
                g_cw2[kk * E2_ + c] = cw[kk * E2_ + p * E_ + j];
            }
        } else {
            #pragma unroll
            for (int h = 0; h < 2; ++h) {
                int c = tid + h * 256;
                int j = c >> 1, p = c & 1;
                g_cb2[c] = cb[p * E_ + j];
            }
        }
        return;
    }
    bid -= NB_PREP;

    // ---- transpose dec -> g_decT[b][e][s] ----
    {
        __shared__ float tile[32][33];
        int s0 = (bid & 15) << 5;
        int e0 = ((bid >> 4) & 7) << 5;
        int b  = bid >> 7;
        int tx = tid & 31, ty = tid >> 5;
        #pragma unroll
        for (int i = 0; i < 32; i += 8)
            tile[ty + i][tx] = dec[((b << 9) + s0 + ty + i) * E_ + e0 + tx];
        __syncthreads();
        #pragma unroll
        for (int i = 0; i < 32; i += 8)
            g_decT[((b << 8) + e0 + ty + i) * HW_ + s0 + tx] = tile[tx][ty + i];
    }
}

// ---------------------------------------------------------------------------
// K1: conv split-(k,ci-half) GEMM -> g_part[kk], kk = 2k + ci_half (0..5)
// grid 768 = kk(6) x b(16) x n-tile(8); 256 threads; thread tile 4m x 4n
// K per CTA = 128 (8 chunks of 16)
// ---------------------------------------------------------------------------
__global__ __launch_bounds__(256) void k_conv4() {
    __shared__ __align__(16) float As[2][16][68];
    __shared__ __align__(16) float Bs[2][16][68];

    int bid = blockIdx.x;
    int nt  = bid & 7;
    int bb  = (bid >> 3) & 15;
    int kk  = bid >> 7;                  // 0..5
    int k   = kk >> 1;                   // conv tap 0..2
    int chf = kk & 1;                    // ci half
    int cib = chf << 7;                  // ci base: 0 or 128
    int n0  = nt << 6;

    int tid = threadIdx.x;
    int kcL = tid >> 4, qL = tid & 15;
    int mi  = tid >> 4, ni = tid & 15;

    const float* aTb = g_aT + bb * (E_ * T_) + cib * T_;
    const float* wB  = g_cw2 + (k * E_ + cib) * E2_ + n0;

    int mb = 4 * qL + 1 - k;

    {
        float4 va = *(const float4*)&aTb[kcL * T_ + 4 * qL];
        float4 vb = *(const float4*)&wB[kcL * E2_ + 4 * qL];
        *(float4*)&Bs[0][kcL][4 * qL] = vb;
        float av[4] = {va.x, va.y, va.z, va.w};
        #pragma unroll
        for (int j = 0; j < 4; ++j) {
            int m = mb + j;
            if ((unsigned)m < 64u) As[0][kcL][m] = av[j];
        }
        if (k == 0 && qL == 0)  As[0][kcL][0]  = 0.f;
        if (k == 2 && qL == 15) As[0][kcL][63] = 0.f;
    }
    __syncthreads();

    ull acc[2][4];
    #pragma unroll
    for (int p = 0; p < 2; ++p)
        #pragma unroll
        for (int j = 0; j < 4; ++j) acc[p][j] = pack2(0.f, 0.f);

    float4 vaN, vbN;
    for (int ch = 0; ch < 8; ++ch) {
        int cur = ch & 1;
        if (ch < 7) {
            int ci0 = (ch + 1) << 4;
            vaN = *(const float4*)&aTb[(ci0 + kcL) * T_ + 4 * qL];
            vbN = *(const float4*)&wB[(ci0 + kcL) * E2_ + 4 * qL];
        }

        #pragma unroll
        for (int kc = 0; kc < 16; ++kc) {
            ulonglong2 av = *(const ulonglong2*)&As[cur][kc][4 * mi];
            float4     bv = *(const float4*)    &Bs[cur][kc][4 * ni];
            ull b0 = pack2(bv.x, bv.x);
            ull b1 = pack2(bv.y, bv.y);
            ull b2 = pack2(bv.z, bv.z);
            ull b3 = pack2(bv.w, bv.w);
            acc[0][0] = ffma2(av.x, b0, acc[0][0]);
            acc[0][1] = ffma2(av.x, b1, acc[0][1]);
            acc[0][2] = ffma2(av.x, b2, acc[0][2]);
            acc[0][3] = ffma2(av.x, b3, acc[0][3]);
            acc[1][0] = ffma2(av.y, b0, acc[1][0]);
            acc[1][1] = ffma2(av.y, b1, acc[1][1]);
            acc[1][2] = ffma2(av.y, b2, acc[1][2]);
            acc[1][3] = ffma2(av.y, b3, acc[1][3]);
        }

        if (ch < 7) {
            int nxt = cur ^ 1;
            *(float4*)&Bs[nxt][kcL][4 * qL] = vbN;
            float av[4] = {vaN.x, vaN.y, vaN.z, vaN.w};
            #pragma unroll
            for (int j = 0; j < 4; ++j) {
                int m = mb + j;
                if ((unsigned)m < 64u) As[nxt][kcL][m] = av[j];
            }
            if (k == 0 && qL == 0)  As[nxt][kcL][0]  = 0.f;
            if (k == 2 && qL == 15) As[nxt][kcL][63] = 0.f;
        }
        __syncthreads();
    }

    float* pb = g_part + (size_t)kk * BT_ * E2_ + ((bb << 6) + 4 * mi) * E2_ + n0 + 4 * ni;
    #pragma unroll
    for (int p = 0; p < 2; ++p) {
        float l0, h0, l1, h1, l2, h2, l3, h3;
        unpack2(acc[p][0], l0, h0);
        unpack2(acc[p][1], l1, h1);
        unpack2(acc[p][2], l2, h2);
        unpack2(acc[p][3], l3, h3);
        float* r0 = pb + (2 * p) * E2_;
        *(float4*)r0         = make_float4(l0, l1, l2, l3);
        *(float4*)(r0 + E2_) = make_float4(h0, h1, h2, h3);
    }
}

// ---------------------------------------------------------------------------
// K1b: reduce 6 partials + bias + GLU -> g_z
// ---------------------------------------------------------------------------
__global__ __launch_bounds__(256) void k_glu() {
    int row = blockIdx.x, j = threadIdx.x;
    size_t off = (size_t)row * E2_ + 2 * j;
    float za, zb;
    {
        float2 p = *(const float2*)&g_part[off];
        za = p.x; zb = p.y;
    }
    #pragma unroll
    for (int kk = 1; kk < 6; ++kk) {
        float2 p = *(const float2*)&g_part[off + (size_t)kk * BT_ * E2_];
        za += p.x; zb += p.y;
    }
    float2 bb = *(const float2*)&g_cb2[2 * j];
    za += bb.x; zb += bb.y;
    g_z[row * E_ + j] = za / (1.f + expf(-zb));
}

// ---------------------------------------------------------------------------
// K2a: h partials: split-K GEMM  C[row][o] += z[row][k-qtr] @ Wt[k-qtr][o]
// grid 256 = kq(4) x row-tile(16 of 64) x o-tile(4 of 64); 256 threads
// K per CTA = 64 (4 chunks of 16); same skeleton as k_conv4
// ---------------------------------------------------------------------------
__global__ __launch_bounds__(256) void k_hgemm() {
    __shared__ __align__(16) float As[2][16][68];
    __shared__ __align__(16) float Bs[2][16][68];

    int bid  = blockIdx.x;
    int ot   = bid & 3;
    int rt   = (bid >> 2) & 15;
    int kq   = bid >> 6;                 // 0..3
    int row0 = rt << 6;
    int o0   = ot << 6;
    int k0   = kq << 6;

    int tid = threadIdx.x;
    int mA  = tid >> 2, qA = tid & 3;
    int kcL = tid >> 4, qL = tid & 15;
    int mi  = tid >> 4, ni = tid & 15;

    const float* zb = g_z + row0 * E_ + k0;
    const float* wB = g_Wt + k0 * E_ + o0;

    {
        float4 va = *(const float4*)&zb[mA * E_ + 4 * qA];
        As[0][4 * qA + 0][mA] = va.x;
        As[0][4 * qA + 1][mA] = va.y;
        As[0][4 * qA + 2][mA] = va.z;
        As[0][4 * qA + 3][mA] = va.w;
        float4 vb = *(const float4*)&wB[kcL * E_ + 4 * qL];
        *(float4*)&Bs[0][kcL][4 * qL] = vb;
    }
    __syncthreads();

    ull acc[2][4];
    #pragma unroll
    for (int p = 0; p < 2; ++p)
        #pragma unroll
        for (int j = 0; j < 4; ++j) acc[p][j] = pack2(0.f, 0.f);

    float4 vaN, vbN;
    #pragma unroll
    for (int ch = 0; ch < 4; ++ch) {
        int cur = ch & 1;
        if (ch < 3) {
            int ci0 = (ch + 1) << 4;
            vaN = *(const float4*)&zb[mA * E_ + ci0 + 4 * qA];
            vbN = *(const float4*)&wB[(ci0 + kcL) * E_ + 4 * qL];
        }

        #pragma unroll
        for (int kc = 0; kc < 16; ++kc) {
            ulonglong2 av = *(const ulonglong2*)&As[cur][kc][4 * mi];
            float4     bv = *(const float4*)    &Bs[cur][kc][4 * ni];
            ull b0 = pack2(bv.x, bv.x);
            ull b1 = pack2(bv.y, bv.y);
            ull b2 = pack2(bv.z, bv.z);
            ull b3 = pack2(bv.w, bv.w);
            acc[0][0] = ffma2(av.x, b0, acc[0][0]);
            acc[0][1] = ffma2(av.x, b1, acc[0][1]);
            acc[0][2] = ffma2(av.x, b2, acc[0][2]);
            acc[0][3] = ffma2(av.x, b3, acc[0][3]);
            acc[1][0] = ffma2(av.y, b0, acc[1][0]);
            acc[1][1] = ffma2(av.y, b1, acc[1][1]);
            acc[1][2] = ffma2(av.y, b2, acc[1][2]);
            acc[1][3] = ffma2(av.y, b3, acc[1][3]);
        }

        if (ch < 3) {
            int nxt = cur ^ 1;
            As[nxt][4 * qA + 0][mA] = vaN.x;
            As[nxt][4 * qA + 1][mA] = vaN.y;
            As[nxt][4 * qA + 2][mA] = vaN.z;
            As[nxt][4 * qA + 3][mA] = vaN.w;
            *(float4*)&Bs[nxt][kcL][4 * qL] = vbN;
        }
        __syncthreads();
    }

    float* pb = g_hpart + (size_t)kq * BT_ * E_ + (row0 + 4 * mi) * E_ + o0 + 4 * ni;
    #pragma unroll
    for (int p = 0; p < 2; ++p) {
        float l0, h0, l1, h1, l2, h2, l3, h3;
        unpack2(acc[p][0], l0, h0);
        unpack2(acc[p][1], l1, h1);
        unpack2(acc[p][2], l2, h2);
        unpack2(acc[p][3], l3, h3);
        float* r0 = pb + (2 * p) * E_;
        *(float4*)r0        = make_float4(l0, l1, l2, l3);
        *(float4*)(r0 + E_) = make_float4(h0, h1, h2, h3);
    }
}

// ---------------------------------------------------------------------------
// K2b: scores + softmax -> g_alpha  (h finalized inline from hpart)
// grid 128 (8 t-rows per CTA); 512 threads; thread owns s = tid
// ---------------------------------------------------------------------------
__global__ __launch_bounds__(512) void k_scores(const float* __restrict__ Wb) {
    __shared__ __align__(16) float qt [E_][8];
    __shared__ __align__(16) float sst[HW_][8];
    __shared__ float redM[8][2], redS[8][2], Iv[8];

    int row0 = blockIdx.x << 3;          // 8 rows, never crosses b (64 | 8)
    int b    = row0 >> 6;
    int tid  = threadIdx.x;
    int lane = tid & 31;
    int w    = tid >> 5;                 // 0..15

    // ---- fused h finalize: qt[e][r] = Σ hpart + Wb + s ----
    {
        int e  = tid & 255;
        int rh = tid >> 8;               // 0/1
        float wb = Wb[e];
        #pragma unroll
        for (int j = 0; j < 4; ++j) {
            int r = rh * 4 + j;
            size_t o = (size_t)(row0 + r) * E_ + e;
            float h = g_hpart[o]
                    + g_hpart[(size_t)BT_ * E_ + o]
                    + g_hpart[(size_t)2 * BT_ * E_ + o]
                    + g_hpart[(size_t)3 * BT_ * E_ + o]
                    + wb + g_s[o];
            qt[e][r] = h;
        }
    }
    __syncthreads();

    const float* kb = g_decT + ((size_t)b << 8) * HW_ + tid;
    ull A[4];
    #pragma unroll
    for (int j = 0; j < 4; ++j) A[j] = pack2(0.f, 0.f);

    #pragma unroll 8
    for (int e = 0; e < E_; ++e) {
        float kv = kb[e * HW_];
        ull kp = pack2(kv, kv);
        ulonglong2 q01 = *(const ulonglong2*)&qt[e][0];
        ulonglong2 q23 = *(const ulonglong2*)&qt[e][4];
        A[0] = ffma2(q01.x, kp, A[0]);
        A[1] = ffma2(q01.y, kp, A[1]);
        A[2] = ffma2(q23.x, kp, A[2]);
        A[3] = ffma2(q23.y, kp, A[3]);
    }
    {
        ull* sp = (ull*)&sst[tid][0];
        #pragma unroll
        for (int j = 0; j < 4; ++j) sp[j] = A[j];
    }
    __syncthreads();

    // softmax: warp w handles t = w&7, s-half = w>>3 (256 s each)
    int t  = w & 7;
    int sh = (w >> 3) << 8;
    float m = -1e30f;
    #pragma unroll
    for (int k = 0; k < 8; ++k)
        m = fmaxf(m, sst[sh + k * 32 + lane][t]);
    #pragma unroll
    for (int off = 16; off; off >>= 1)
        m = fmaxf(m, __shfl_xor_sync(0xffffffffu, m, off));
    if (lane == 0) redM[t][w >> 3] = m;
    __syncthreads();
    float M = fmaxf(redM[t][0], redM[t][1]);

    float sum = 0.f;
    #pragma unroll
    for (int k = 0; k < 8; ++k) {
        int s = sh + k * 32 + lane;
        float ev = expf(sst[s][t] - M);
        sst[s][t] = ev;
        sum += ev;
    }
    #pragma unroll
    for (int off = 16; off; off >>= 1)
        sum += __shfl_xor_sync(0xffffffffu, sum, off);
    if (lane == 0) redS[t][w >> 3] = sum;
    __syncthreads();
    if (tid < 8) Iv[tid] = 1.f / (redS[tid][0] + redS[tid][1]);
    __syncthreads();

    #pragma unroll
    for (int r = 0; r < 8; ++r)
        g_alpha[(size_t)(row0 + r) * HW_ + tid] = sst[tid][r] * Iv[r];
}

// ---------------------------------------------------------------------------
// K2c: ctx partials: c_part[sc] = alpha[:, sc-chunk] @ res[sc-chunk]
// grid 512 = b(16) x t-tile(8) x s-chunk(4); 256 threads (thread = e)
// ---------------------------------------------------------------------------
__global__ __launch_bounds__(256) void k_ctx() {
    __shared__ __align__(16) float al[128][8];

    int bid  = blockIdx.x;
    int sc   = bid & 3;
    int tt   = (bid >> 2) & 7;
    int b    = bid >> 5;
    int sb   = sc << 7;
    int row0 = (b << 6) + (tt << 3);
    int tid  = threadIdx.x;
    int lane = tid & 31;
    int wid  = tid >> 5;

    {
        float4 av = *(const float4*)&g_alpha[(size_t)(row0 + wid) * HW_ + sb + 4 * lane];
        al[4 * lane + 0][wid] = av.x;
        al[4 * lane + 1][wid] = av.y;
        al[4 * lane + 2][wid] = av.z;
        al[4 * lane + 3][wid] = av.w;
    }
    __syncthreads();

    const float* resb = g_res + ((size_t)b * HW_ + sb) * E_ + tid;
    ull acc[4];
    #pragma unroll
    for (int p = 0; p < 4; ++p) acc[p] = pack2(0.f, 0.f);

    #pragma unroll 8
    for (int s = 0; s < 128; ++s) {
        float rv = resb[(size_t)s * E_];
        ull rp = pack2(rv, rv);
        ulonglong2 a01 = *(const ulonglong2*)&al[s][0];
        ulonglong2 a23 = *(const ulonglong2*)&al[s][4];
        acc[0] = ffma2(a01.x, rp, acc[0]);
        acc[1] = ffma2(a01.y, rp, acc[1]);
        acc[2] = ffma2(a23.x, rp, acc[2]);
        acc[3] = ffma2(a23.y, rp, acc[3]);
    }

    float* cp = g_cpart + ((size_t)sc * BT_ + row0) * E_ + tid;
    #pragma unroll
    for (int p = 0; p < 4; ++p) {
        float c0, c1; unpack2(acc[p], c0, c1);
        cp[(2 * p) * E_]     = c0;
        cp[(2 * p + 1) * E_] = c1;
    }
}

// ---------------------------------------------------------------------------
// K2d: a = sum(c_part) + z  -> g_a, g_aT
// ---------------------------------------------------------------------------
__global__ __launch_bounds__(256) void k_afin() {
    int bid  = blockIdx.x;
    int b    = bid >> 3;
    int t0   = (bid & 7) << 3;
    int row0 = (b << 6) + t0;
    int e    = threadIdx.x;

    float av8[8];
    #pragma unroll
    for (int r = 0; r < 8; ++r) {
        size_t o = (size_t)(row0 + r) * E_ + e;
        float c = g_cpart[o]
                + g_cpart[(size_t)BT_ * E_ + o]
                + g_cpart[(size_t)2 * BT_ * E_ + o]
                + g_cpart[(size_t)3 * BT_ * E_ + o];
        float v = c + g_z[o];
        g_a[o] = v;
        av8[r] = v;
    }
    float* atp = g_aT + b * (E_ * T_) + e * T_ + t0;
    *(float4*)atp       = make_float4(av8[0], av8[1], av8[2], av8[3]);
    *(float4*)(atp + 4) = make_float4(av8[4], av8[5], av8[6], av8[7]);
}

// ---------------------------------------------------------------------------
// K3: logits = a @ Wo^T + Wo_b; log_softmax over V  -> out
// ---------------------------------------------------------------------------
__global__ __launch_bounds__(128) void k_logits(const float* __restrict__ Wob,
                                                float* __restrict__ out) {
    __shared__ __align__(16) float av4[4][E_];
    __shared__ float redm[4][4], reds[4][4];

    int row0 = blockIdx.x * 4;
    int v    = threadIdx.x;
    int lane = v & 31;
    int wid  = v >> 5;

    #pragma unroll
    for (int r = 0; r < 4; ++r) {
        av4[r][v]       = g_a[(row0 + r) * E_ + v];
        av4[r][v + 128] = g_a[(row0 + r) * E_ + v + 128];
    }
    __syncthreads();

    ull acc[4];
    #pragma unroll
    for (int r = 0; r < 4; ++r) acc[r] = pack2(0.f, 0.f);

    const ull* wop = (const ull*)g_Wop;
    #pragma unroll 4
    for (int ep = 0; ep < E_ / 2; ++ep) {
        ull wp = wop[ep * V_ + v];
        #pragma unroll
        for (int r = 0; r < 4; ++r)
            acc[r] = ffma2(((const ull*)av4[r])[ep], wp, acc[r]);
    }

    float lg[4], wb = Wob[v];
    #pragma unroll
    for (int r = 0; r < 4; ++r) {
        float lo, hi; unpack2(acc[r], lo, hi);
        lg[r] = lo + hi + wb;
    }

    float wm[4];
    #pragma unroll
    for (int r = 0; r < 4; ++r) {
        wm[r] = lg[r];
        #pragma unroll
        for (int off = 16; off; off >>= 1)
            wm[r] = fmaxf(wm[r], __shfl_xor_sync(0xffffffffu, wm[r], off));
    }
    if (lane == 0) {
        #pragma unroll
        for (int r = 0; r < 4; ++r) redm[r][wid] = wm[r];
    }
    __syncthreads();
    float bm[4];
    #pragma unroll
    for (int r = 0; r < 4; ++r)
        bm[r] = fmaxf(fmaxf(redm[r][0], redm[r][1]), fmaxf(redm[r][2], redm[r][3]));

    float ws[4];
    #pragma unroll
    for (int r = 0; r < 4; ++r) {
        ws[r] = expf(lg[r] - bm[r]);
        #pragma unroll
        for (int off = 16; off; off >>= 1)
            ws[r] += __shfl_xor_sync(0xffffffffu, ws[r], off);
    }
    if (lane == 0) {
        #pragma unroll
        for (int r = 0; r < 4; ++r) reds[r][wid] = ws[r];
    }
    __syncthreads();

    #pragma unroll
    for (int r = 0; r < 4; ++r) {
        float bs = reds[r][0] + reds[r][1] + reds[r][2] + reds[r][3];
        out[(row0 + r) * V_ + v] = lg[r] - bm[r] - logf(bs);
    }
}

// ---------------------------------------------------------------------------
// kernel_launch
// ---------------------------------------------------------------------------
extern "C" void kernel_launch(void* const* d_in, const int* in_sizes, int n_in,
                              void* d_out, int out_size) {
    int li = 2;
    for (int i = 0; i < n_in; ++i)
        if (in_sizes[i] == 1024) { li = i; break; }

    const float *enc, *dec, *emb, *cw, *cb, *Ww, *Wb, *Wo, *Wob;
    const int* labels;
    if (li == 2) {
        enc = (const float*)d_in[0]; dec = (const float*)d_in[1];
        labels = (const int*)d_in[2];
        emb = (const float*)d_in[3]; cw  = (const float*)d_in[4];
        cb  = (const float*)d_in[5]; Ww  = (const float*)d_in[6];
        Wb  = (const float*)d_in[7]; Wo  = (const float*)d_in[8];
        Wob = (const float*)d_in[9];
    } else {
        enc = (const float*)d_in[0]; dec = (const float*)d_in[1];
        emb = (const float*)d_in[2]; cw  = (const float*)d_in[3];
        cb  = (const float*)d_in[4]; Ww  = (const float*)d_in[5];
        Wb  = (const float*)d_in[6]; Wo  = (const float*)d_in[7];
        Wob = (const float*)d_in[8];
        labels = (const int*)d_in[9];
    }
    float* out = (float*)d_out;

    k_setup<<<NB_EMB + NB_RES + NB_PREP + NB_TR, 256>>>(labels, emb, enc, dec,
                                                        Ww, Wo, cw, cb);

    for (int l = 0; l < NBLK_; ++l) {
        k_conv4 <<<768, 256>>>();
        k_glu   <<<BT_, 256>>>();
        k_hgemm <<<256, 256>>>();
        k_scores<<<128, 512>>>(Wb);
        k_ctx   <<<512, 256>>>();
        k_afin  <<<128, 256>>>();
    }

    k_logits<<<BT_ / 4, 128>>>(Wob, out);
}

// round 11
// speedup vs baseline: 2.1462x; 1.1376x over previous
#include <cuda_runtime.h>
#include <math.h>

// ---------------------------------------------------------------------------
// Problem constants
// ---------------------------------------------------------------------------
#define B_    16
#define T_    64
#define HW_   512
#define E_    256
#define E2_   512
#define V_    128
#define BT_   1024   // B*T
#define NBLK_ 3

typedef unsigned long long ull;

// ---------------------------------------------------------------------------
// Scratch (device globals: no allocation allowed)
// ---------------------------------------------------------------------------
__device__ __align__(16) float g_s    [BT_ * E_];       // embed(labels), fixed
__device__ __align__(16) float g_a    [BT_ * E_];       // running activation (row-major)
__device__ __align__(16) float g_aT   [B_ * E_ * T_];   // a transposed [b][e][t]
__device__ __align__(16) float g_z    [BT_ * E_];       // GLU output
__device__ __align__(16) float g_res  [B_ * HW_ * E_];  // enc + dec
__device__ __align__(16) float g_Wt   [E_ * E_];        // W_w transposed: Wt[i][o]
__device__ __align__(16) float g_Wop  [E_ * V_];        // Wo interleaved e-pairs
__device__ __align__(16) float g_cw2  [3 * E_ * E2_];   // conv_w, GLU-interleaved cols
__device__ __align__(16) float g_cb2  [E2_];            // conv_b, interleaved
__device__ __align__(16) float g_decT [B_ * E_ * HW_];  // dec transposed [b][e][s]
__device__ __align__(16) float g_part [6 * BT_ * E2_];  // conv split-k partials
__device__ __align__(16) float g_hpart[4 * BT_ * E_];   // hproj split-k partials

// ---------------------------------------------------------------------------
// f32x2 packed math (sm_100+)
// ---------------------------------------------------------------------------
__device__ __forceinline__ ull pack2(float x, float y) {
    ull r; asm("mov.b64 %0, {%1,%2};" : "=l"(r) : "f"(x), "f"(y)); return r;
}
__device__ __forceinline__ void unpack2(ull v, float& x, float& y) {
    asm("mov.b64 {%0,%1}, %2;" : "=f"(x), "=f"(y) : "l"(v));
}
__device__ __forceinline__ ull ffma2(ull a, ull b, ull c) {
    ull d; asm("fma.rn.f32x2 %0, %1, %2, %3;" : "=l"(d) : "l"(a), "l"(b), "l"(c)); return d;
}

// ---------------------------------------------------------------------------
// K0: merged setup — embed | residual | weight-prep | dec transpose
// ---------------------------------------------------------------------------
#define NB_EMB  1024
#define NB_RES  2048
#define NB_PREP 1153
#define NB_TR   2048

__global__ __launch_bounds__(256) void k_setup(const int* __restrict__ labels,
                                               const float* __restrict__ emb,
                                               const float* __restrict__ enc,
                                               const float* __restrict__ dec,
                                               const float* __restrict__ Ww,
                                               const float* __restrict__ Wo,
                                               const float* __restrict__ cw,
                                               const float* __restrict__ cb) {
    int bid = blockIdx.x, tid = threadIdx.x;

    if (bid < NB_EMB) {
        int row = bid, e = tid;
        int lbl = labels[row];
        float v = emb[lbl * E_ + e];
        g_s[row * E_ + e] = v;
        g_a[row * E_ + e] = v;
        g_aT[(row >> 6) * (E_ * T_) + e * T_ + (row & 63)] = v;
        return;
    }
    bid -= NB_EMB;

    if (bid < NB_RES) {
        int i = bid * 256 + tid;
        float4 a = ((const float4*)enc)[i];
        float4 b = ((const float4*)dec)[i];
        float4 c;
        c.x = a.x + b.x; c.y = a.y + b.y; c.z = a.z + b.z; c.w = a.w + b.w;
        ((float4*)g_res)[i] = c;
        return;
    }
    bid -= NB_RES;

    if (bid < NB_PREP) {
        if (bid < E_) {
            g_Wt[tid * E_ + bid] = Ww[bid * E_ + tid];
        } else if (bid < E_ + V_) {
            int v = bid - E_;
            g_Wop[(tid >> 1) * (2 * V_) + 2 * v + (tid & 1)] = Wo[v * E_ + tid];
        } else if (bid < E_ + V_ + 3 * E_) {
            int kk = bid - (E_ + V_);
            #pragma unroll
            for (int h = 0; h < 2; ++h) {
                int c = tid + h * 256;
                int j = c >> 1, p = c & 1;
                g_cw2[kk * E2_ + c] = cw[kk * E2_ + p * E_ + j];
            }
        } else {
            #pragma unroll
            for (int h = 0; h < 2; ++h) {
                int c = tid + h * 256;
                int j = c >> 1, p = c & 1;
                g_cb2[c] = cb[p * E_ + j];
            }
        }
        return;
    }
    bid -= NB_PREP;

    // ---- transpose dec -> g_decT[b][e][s] ----
    {
        __shared__ float tile[32][33];
        int s0 = (bid & 15) << 5;
        int e0 = ((bid >> 4) & 7) << 5;
        int b  = bid >> 7;
        int tx = tid & 31, ty = tid >> 5;
        #pragma unroll
        for (int i = 0; i < 32; i += 8)
            tile[ty + i][tx] = dec[((b << 9) + s0 + ty + i) * E_ + e0 + tx];
        __syncthreads();
        #pragma unroll
        for (int i = 0; i < 32; i += 8)
            g_decT[((b << 8) + e0 + ty + i) * HW_ + s0 + tx] = tile[tx][ty + i];
    }
}

// ---------------------------------------------------------------------------
// K1: conv split-(k,ci-half) GEMM -> g_part[kk], kk = 2k + ci_half (0..5)
// grid 768 = kk(6) x b(16) x n-tile(8); 256 threads; thread tile 4m x 4n
// ---------------------------------------------------------------------------
__global__ __launch_bounds__(256) void k_conv4() {
    __shared__ __align__(16) float As[2][16][68];
    __shared__ __align__(16) float Bs[2][16][68];

    int bid = blockIdx.x;
    int nt  = bid & 7;
    int bb  = (bid >> 3) & 15;
    int kk  = bid >> 7;                  // 0..5
    int k   = kk >> 1;                   // conv tap 0..2
    int cib = (kk & 1) << 7;             // ci base: 0 or 128
    int n0  = nt << 6;

    int tid = threadIdx.x;
    int kcL = tid >> 4, qL = tid & 15;
    int mi  = tid >> 4, ni = tid & 15;

    const float* aTb = g_aT + bb * (E_ * T_) + cib * T_;
    const float* wB  = g_cw2 + (k * E_ + cib) * E2_ + n0;

    int mb = 4 * qL + 1 - k;

    {
        float4 va = *(const float4*)&aTb[kcL * T_ + 4 * qL];
        float4 vb = *(const float4*)&wB[kcL * E2_ + 4 * qL];
        *(float4*)&Bs[0][kcL][4 * qL] = vb;
        float av[4] = {va.x, va.y, va.z, va.w};
        #pragma unroll
        for (int j = 0; j < 4; ++j) {
            int m = mb + j;
            if ((unsigned)m < 64u) As[0][kcL][m] = av[j];
        }
        if (k == 0 && qL == 0)  As[0][kcL][0]  = 0.f;
        if (k == 2 && qL == 15) As[0][kcL][63] = 0.f;
    }
    __syncthreads();

    ull acc[2][4];
    #pragma unroll
    for (int p = 0; p < 2; ++p)
        #pragma unroll
        for (int j = 0; j < 4; ++j) acc[p][j] = pack2(0.f, 0.f);

    float4 vaN, vbN;
    for (int ch = 0; ch < 8; ++ch) {
        int cur = ch & 1;
        if (ch < 7) {
            int ci0 = (ch + 1) << 4;
            vaN = *(const float4*)&aTb[(ci0 + kcL) * T_ + 4 * qL];
            vbN = *(const float4*)&wB[(ci0 + kcL) * E2_ + 4 * qL];
        }

        #pragma unroll
        for (int kc = 0; kc < 16; ++kc) {
            ulonglong2 av = *(const ulonglong2*)&As[cur][kc][4 * mi];
            float4     bv = *(const float4*)    &Bs[cur][kc][4 * ni];
            ull b0 = pack2(bv.x, bv.x);
            ull b1 = pack2(bv.y, bv.y);
            ull b2 = pack2(bv.z, bv.z);
            ull b3 = pack2(bv.w, bv.w);
            acc[0][0] = ffma2(av.x, b0, acc[0][0]);
            acc[0][1] = ffma2(av.x, b1, acc[0][1]);
            acc[0][2] = ffma2(av.x, b2, acc[0][2]);
            acc[0][3] = ffma2(av.x, b3, acc[0][3]);
            acc[1][0] = ffma2(av.y, b0, acc[1][0]);
            acc[1][1] = ffma2(av.y, b1, acc[1][1]);
            acc[1][2] = ffma2(av.y, b2, acc[1][2]);
            acc[1][3] = ffma2(av.y, b3, acc[1][3]);
        }

        if (ch < 7) {
            int nxt = cur ^ 1;
            *(float4*)&Bs[nxt][kcL][4 * qL] = vbN;
            float av[4] = {vaN.x, vaN.y, vaN.z, vaN.w};
            #pragma unroll
            for (int j = 0; j < 4; ++j) {
                int m = mb + j;
                if ((unsigned)m < 64u) As[nxt][kcL][m] = av[j];
            }
            if (k == 0 && qL == 0)  As[nxt][kcL][0]  = 0.f;
            if (k == 2 && qL == 15) As[nxt][kcL][63] = 0.f;
        }
        __syncthreads();
    }

    float* pb = g_part + (size_t)kk * BT_ * E2_ + ((bb << 6) + 4 * mi) * E2_ + n0 + 4 * ni;
    #pragma unroll
    for (int p = 0; p < 2; ++p) {
        float l0, h0, l1, h1, l2, h2, l3, h3;
        unpack2(acc[p][0], l0, h0);
        unpack2(acc[p][1], l1, h1);
        unpack2(acc[p][2], l2, h2);
        unpack2(acc[p][3], l3, h3);
        float* r0 = pb + (2 * p) * E2_;
        *(float4*)r0         = make_float4(l0, l1, l2, l3);
        *(float4*)(r0 + E2_) = make_float4(h0, h1, h2, h3);
    }
}

// ---------------------------------------------------------------------------
// K1b: reduce 6 partials + bias + GLU -> g_z
// ---------------------------------------------------------------------------
__global__ __launch_bounds__(256) void k_glu() {
    int row = blockIdx.x, j = threadIdx.x;
    size_t off = (size_t)row * E2_ + 2 * j;
    float za, zb;
    {
        float2 p = *(const float2*)&g_part[off];
        za = p.x; zb = p.y;
    }
    #pragma unroll
    for (int kk = 1; kk < 6; ++kk) {
        float2 p = *(const float2*)&g_part[off + (size_t)kk * BT_ * E2_];
        za += p.x; zb += p.y;
    }
    float2 bb = *(const float2*)&g_cb2[2 * j];
    za += bb.x; zb += bb.y;
    g_z[row * E_ + j] = za / (1.f + expf(-zb));
}

// ---------------------------------------------------------------------------
// K2a: h partials: split-K GEMM  C[row][o] += z[row][k-qtr] @ Wt[k-qtr][o]
// grid 256 = kq(4) x row-tile(16 of 64) x o-tile(4 of 64); 256 threads
// ---------------------------------------------------------------------------
__global__ __launch_bounds__(256) void k_hgemm() {
    __shared__ __align__(16) float As[2][16][68];
    __shared__ __align__(16) float Bs[2][16][68];

    int bid  = blockIdx.x;
    int ot   = bid & 3;
    int rt   = (bid >> 2) & 15;
    int kq   = bid >> 6;                 // 0..3
    int row0 = rt << 6;
    int o0   = ot << 6;
    int k0   = kq << 6;

    int tid = threadIdx.x;
    int mA  = tid >> 2, qA = tid & 3;
    int kcL = tid >> 4, qL = tid & 15;
    int mi  = tid >> 4, ni = tid & 15;

    const float* zb = g_z + row0 * E_ + k0;
    const float* wB = g_Wt + k0 * E_ + o0;

    {
        float4 va = *(const float4*)&zb[mA * E_ + 4 * qA];
        As[0][4 * qA + 0][mA] = va.x;
        As[0][4 * qA + 1][mA] = va.y;
        As[0][4 * qA + 2][mA] = va.z;
        As[0][4 * qA + 3][mA] = va.w;
        float4 vb = *(const float4*)&wB[kcL * E_ + 4 * qL];
        *(float4*)&Bs[0][kcL][4 * qL] = vb;
    }
    __syncthreads();

    ull acc[2][4];
    #pragma unroll
    for (int p = 0; p < 2; ++p)
        #pragma unroll
        for (int j = 0; j < 4; ++j) acc[p][j] = pack2(0.f, 0.f);

    float4 vaN, vbN;
    #pragma unroll
    for (int ch = 0; ch < 4; ++ch) {
        int cur = ch & 1;
        if (ch < 3) {
            int ci0 = (ch + 1) << 4;
            vaN = *(const float4*)&zb[mA * E_ + ci0 + 4 * qA];
            vbN = *(const float4*)&wB[(ci0 + kcL) * E_ + 4 * qL];
        }

        #pragma unroll
        for (int kc = 0; kc < 16; ++kc) {
            ulonglong2 av = *(const ulonglong2*)&As[cur][kc][4 * mi];
            float4     bv = *(const float4*)    &Bs[cur][kc][4 * ni];
            ull b0 = pack2(bv.x, bv.x);
            ull b1 = pack2(bv.y, bv.y);
            ull b2 = pack2(bv.z, bv.z);
            ull b3 = pack2(bv.w, bv.w);
            acc[0][0] = ffma2(av.x, b0, acc[0][0]);
            acc[0][1] = ffma2(av.x, b1, acc[0][1]);
            acc[0][2] = ffma2(av.x, b2, acc[0][2]);
            acc[0][3] = ffma2(av.x, b3, acc[0][3]);
            acc[1][0] = ffma2(av.y, b0, acc[1][0]);
            acc[1][1] = ffma2(av.y, b1, acc[1][1]);
            acc[1][2] = ffma2(av.y, b2, acc[1][2]);
            acc[1][3] = ffma2(av.y, b3, acc[1][3]);
        }

        if (ch < 3) {
            int nxt = cur ^ 1;
            As[nxt][4 * qA + 0][mA] = vaN.x;
            As[nxt][4 * qA + 1][mA] = vaN.y;
            As[nxt][4 * qA + 2][mA] = vaN.z;
            As[nxt][4 * qA + 3][mA] = vaN.w;
            *(float4*)&Bs[nxt][kcL][4 * qL] = vbN;
        }
        __syncthreads();
    }

    float* pb = g_hpart + (size_t)kq * BT_ * E_ + (row0 + 4 * mi) * E_ + o0 + 4 * ni;
    #pragma unroll
    for (int p = 0; p < 2; ++p) {
        float l0, h0, l1, h1, l2, h2, l3, h3;
        unpack2(acc[p][0], l0, h0);
        unpack2(acc[p][1], l1, h1);
        unpack2(acc[p][2], l2, h2);
        unpack2(acc[p][3], l3, h3);
        float* r0 = pb + (2 * p) * E_;
        *(float4*)r0        = make_float4(l0, l1, l2, l3);
        *(float4*)(r0 + E_) = make_float4(h0, h1, h2, h3);
    }
}

// ---------------------------------------------------------------------------
// K2b: fused attention: h-finalize | scores | softmax | ctx | a=c+z
// grid 128 (8 t-rows per CTA); 512 threads
// ---------------------------------------------------------------------------
__global__ __launch_bounds__(512) void k_attn3(const float* __restrict__ Wb) {
    __shared__ __align__(16) float qt  [E_][8];     // h queries [e][t]   (8 KB)
    __shared__ __align__(16) float sst [HW_][8];    // scores/exp [s][t] (16 KB)
    __shared__ __align__(16) float psum[E_][8];     // ctx partial half-1 (8 KB)
    __shared__ float redM[8][2], redS[8][2], Iv[8];

    int row0 = blockIdx.x << 3;          // 8 rows, never crosses b (64 | 8)
    int b    = row0 >> 6;
    int t0   = row0 & 63;
    int tid  = threadIdx.x;
    int lane = tid & 31;
    int w    = tid >> 5;                 // 0..15
    int e    = tid & 255;
    int half = tid >> 8;                 // 0/1

    // ---- phase 0: fused h finalize: qt[e][r] = Σ hpart + Wb + s ----
    {
        float wb = Wb[e];
        #pragma unroll
        for (int j = 0; j < 4; ++j) {
            int r = half * 4 + j;
            size_t o = (size_t)(row0 + r) * E_ + e;
            float h = g_hpart[o]
                    + g_hpart[(size_t)BT_ * E_ + o]
                    + g_hpart[(size_t)2 * BT_ * E_ + o]
                    + g_hpart[(size_t)3 * BT_ * E_ + o]
                    + wb + g_s[o];
            qt[e][r] = h;
        }
    }
    __syncthreads();

    // ---- phase 1: scores (thread = s = tid) ----
    {
        const float* kb = g_decT + ((size_t)b << 8) * HW_ + tid;
        ull A[4];
        #pragma unroll
        for (int j = 0; j < 4; ++j) A[j] = pack2(0.f, 0.f);

        #pragma unroll 8
        for (int ei = 0; ei < E_; ++ei) {
            float kv = kb[ei * HW_];
            ull kp = pack2(kv, kv);
            ulonglong2 q01 = *(const ulonglong2*)&qt[ei][0];
            ulonglong2 q23 = *(const ulonglong2*)&qt[ei][4];
            A[0] = ffma2(q01.x, kp, A[0]);
            A[1] = ffma2(q01.y, kp, A[1]);
            A[2] = ffma2(q23.x, kp, A[2]);
            A[3] = ffma2(q23.y, kp, A[3]);
        }
        ull* sp = (ull*)&sst[tid][0];
        #pragma unroll
        for (int j = 0; j < 4; ++j) sp[j] = A[j];
    }
    __syncthreads();

    // ---- phase 2: softmax stats (warp w: t = w&7, s-half = w>>3) ----
    {
        int t  = w & 7;
        int sh = (w >> 3) << 8;
        float m = -1e30f;
        #pragma unroll
        for (int k = 0; k < 8; ++k)
            m = fmaxf(m, sst[sh + k * 32 + lane][t]);
        #pragma unroll
        for (int off = 16; off; off >>= 1)
            m = fmaxf(m, __shfl_xor_sync(0xffffffffu, m, off));
        if (lane == 0) redM[t][w >> 3] = m;
        __syncthreads();
        float M = fmaxf(redM[t][0], redM[t][1]);

        float sum = 0.f;
        #pragma unroll
        for (int k = 0; k < 8; ++k) {
            int s = sh + k * 32 + lane;
            float ev = expf(sst[s][t] - M);
            sst[s][t] = ev;
            sum += ev;
        }
        #pragma unroll
        for (int off = 16; off; off >>= 1)
            sum += __shfl_xor_sync(0xffffffffu, sum, off);
        if (lane == 0) redS[t][w >> 3] = sum;
        __syncthreads();
        if (tid < 8) Iv[tid] = 1.f / (redS[tid][0] + redS[tid][1]);
    }
    __syncthreads();

    // ---- phase 3: ctx: thread (e, half) accumulates its 256-s half ----
    {
        const float* resb = g_res + ((size_t)b * HW_ + (half << 8)) * E_ + e;
        int sb = half << 8;
        ull acc[4];
        #pragma unroll
        for (int p = 0; p < 4; ++p) acc[p] = pack2(0.f, 0.f);

        #pragma unroll 8
        for (int s = 0; s < 256; ++s) {
            float rv = resb[(size_t)s * E_];
            ull rp = pack2(rv, rv);
            ulonglong2 a01 = *(const ulonglong2*)&sst[sb + s][0];
            ulonglong2 a23 = *(const ulonglong2*)&sst[sb + s][4];
            acc[0] = ffma2(a01.x, rp, acc[0]);
            acc[1] = ffma2(a01.y, rp, acc[1]);
            acc[2] = ffma2(a23.x, rp, acc[2]);
            acc[3] = ffma2(a23.y, rp, acc[3]);
        }

        if (half == 1) {
            ull* pp = (ull*)&psum[e][0];
            #pragma unroll
            for (int p = 0; p < 4; ++p) pp[p] = acc[p];
        }
        __syncthreads();

        if (half == 0) {
            float av8[8];
            #pragma unroll
            for (int p = 0; p < 4; ++p) {
                float c0, c1; unpack2(acc[p], c0, c1);
                int t = 2 * p;
                size_t idx = (size_t)(row0 + t) * E_ + e;
                float v0 = (c0 + psum[e][t])     * Iv[t]     + g_z[idx];
                float v1 = (c1 + psum[e][t + 1]) * Iv[t + 1] + g_z[idx + E_];
                g_a[idx]      = v0;
                g_a[idx + E_] = v1;
                av8[t] = v0; av8[t + 1] = v1;
            }
            float* atp = g_aT + b * (E_ * T_) + e * T_ + t0;
            *(float4*)atp       = make_float4(av8[0], av8[1], av8[2], av8[3]);
            *(float4*)(atp + 4) = make_float4(av8[4], av8[5], av8[6], av8[7]);
        }
    }
}

// ---------------------------------------------------------------------------
// K3: logits = a @ Wo^T + Wo_b; log_softmax over V  -> out
// ---------------------------------------------------------------------------
__global__ __launch_bounds__(128) void k_logits(const float* __restrict__ Wob,
                                                float* __restrict__ out) {
    __shared__ __align__(16) float av4[4][E_];
    __shared__ float redm[4][4], reds[4][4];

    int row0 = blockIdx.x * 4;
    int v    = threadIdx.x;
    int lane = v & 31;
    int wid  = v >> 5;

    #pragma unroll
    for (int r = 0; r < 4; ++r) {
        av4[r][v]       = g_a[(row0 + r) * E_ + v];
        av4[r][v + 128] = g_a[(row0 + r) * E_ + v + 128];
    }
    __syncthreads();

    ull acc[4];
    #pragma unroll
    for (int r = 0; r < 4; ++r) acc[r] = pack2(0.f, 0.f);

    const ull* wop = (const ull*)g_Wop;
    #pragma unroll 4
    for (int ep = 0; ep < E_ / 2; ++ep) {
        ull wp = wop[ep * V_ + v];
        #pragma unroll
        for (int r = 0; r < 4; ++r)
            acc[r] = ffma2(((const ull*)av4[r])[ep], wp, acc[r]);
    }

    float lg[4], wb = Wob[v];
    #pragma unroll
    for (int r = 0; r < 4; ++r) {
        float lo, hi; unpack2(acc[r], lo, hi);
        lg[r] = lo + hi + wb;
    }

    float wm[4];
    #pragma unroll
    for (int r = 0; r < 4; ++r) {
        wm[r] = lg[r];
        #pragma unroll
        for (int off = 16; off; off >>= 1)
            wm[r] = fmaxf(wm[r], __shfl_xor_sync(0xffffffffu, wm[r], off));
    }
    if (lane == 0) {
        #pragma unroll
        for (int r = 0; r < 4; ++r) redm[r][wid] = wm[r];
    }
    __syncthreads();
    float bm[4];
    #pragma unroll
    for (int r = 0; r < 4; ++r)
        bm[r] = fmaxf(fmaxf(redm[r][0], redm[r][1]), fmaxf(redm[r][2], redm[r][3]));

    float ws[4];
    #pragma unroll
    for (int r = 0; r < 4; ++r) {
        ws[r] = expf(lg[r] - bm[r]);
        #pragma unroll
        for (int off = 16; off; off >>= 1)
            ws[r] += __shfl_xor_sync(0xffffffffu, ws[r], off);
    }
    if (lane == 0) {
        #pragma unroll
        for (int r = 0; r < 4; ++r) reds[r][wid] = ws[r];
    }
    __syncthreads();

    #pragma unroll
    for (int r = 0; r < 4; ++r) {
        float bs = reds[r][0] + reds[r][1] + reds[r][2] + reds[r][3];
        out[(row0 + r) * V_ + v] = lg[r] - bm[r] - logf(bs);
    }
}

// ---------------------------------------------------------------------------
// kernel_launch
// ---------------------------------------------------------------------------
extern "C" void kernel_launch(void* const* d_in, const int* in_sizes, int n_in,
                              void* d_out, int out_size) {
    int li = 2;
    for (int i = 0; i < n_in; ++i)
        if (in_sizes[i] == 1024) { li = i; break; }

    const float *enc, *dec, *emb, *cw, *cb, *Ww, *Wb, *Wo, *Wob;
    const int* labels;
    if (li == 2) {
        enc = (const float*)d_in[0]; dec = (const float*)d_in[1];
        labels = (const int*)d_in[2];
        emb = (const float*)d_in[3]; cw  = (const float*)d_in[4];
        cb  = (const float*)d_in[5]; Ww  = (const float*)d_in[6];
        Wb  = (const float*)d_in[7]; Wo  = (const float*)d_in[8];
        Wob = (const float*)d_in[9];
    } else {
        enc = (const float*)d_in[0]; dec = (const float*)d_in[1];
        emb = (const float*)d_in[2]; cw  = (const float*)d_in[3];
        cb  = (const float*)d_in[4]; Ww  = (const float*)d_in[5];
        Wb  = (const float*)d_in[6]; Wo  = (const float*)d_in[7];
        Wob = (const float*)d_in[8];
        labels = (const int*)d_in[9];
    }
    float* out = (float*)d_out;

    k_setup<<<NB_EMB + NB_RES + NB_PREP + NB_TR, 256>>>(labels, emb, enc, dec,
                                                        Ww, Wo, cw, cb);

    for (int l = 0; l < NBLK_; ++l) {
        k_conv4<<<768, 256>>>();
        k_glu  <<<BT_, 256>>>();
        k_hgemm<<<256, 256>>>();
        k_attn3<<<128, 512>>>(Wb);
    }

    k_logits<<<BT_ / 4, 128>>>(Wob, out);
}